// round 1
// baseline (speedup 1.0000x reference)
#include <cuda_runtime.h>
#include <math.h>

// ---------------------------------------------------------------------------
// Bidirectional LSTM: T=512, B=32, I=1024, H=1024.
// Round 1: pure fp32 baseline.
//   K_init : copy c0 -> g_c
//   K_xg   : xg[d,t,b,g] = sum_i x[t,b,i]*Wih_d[g,i] + bih_d[g] + bhh_d[g]
//   K_step : (x512) gates = xg[t] + h_{t-1} @ Whh^T ; LSTM cell update.
//            h is stored directly in d_out (fp32) and re-read next step.
//   K_fin  : write hf/cf/hb/cb tail.
// ---------------------------------------------------------------------------

namespace {
constexpr int T = 512;
constexpr int B = 32;
constexpr int I = 1024;
constexpr int H = 1024;
constexpr int G4 = 4 * H;          // 4096 gate rows per direction
constexpr int OUT_COLS = 2 * H;    // 2048
constexpr int M_ALL = T * B;       // 16384
constexpr long long OUT_MAIN = (long long)T * B * OUT_COLS;  // 33554432
}

// Scratch (allocations are forbidden; __device__ globals are the sanctioned path)
__device__ float g_xg[2LL * M_ALL * G4];   // [dir][t*B+b][4H]  (536 MB)
__device__ float g_c[2 * B * H];           // cell state per direction

// ---------------------------------------------------------------------------
// Kernel: init cell state
// ---------------------------------------------------------------------------
__global__ void init_c_kernel(const float* __restrict__ c0f,
                              const float* __restrict__ c0b) {
    int i = blockIdx.x * blockDim.x + threadIdx.x;
    if (i < B * H) {
        g_c[i]         = c0f[i];
        g_c[B * H + i] = c0b[i];
    }
}

// ---------------------------------------------------------------------------
// Kernel: xg = X @ W^T + bias, both directions.
// C is [M=16384, N=8192] where n = d*4096 + g. Classic 128x128x8 SGEMM,
// 256 threads, 8x8 per thread, 2 CTAs/SM for load/compute overlap.
// ---------------------------------------------------------------------------
__global__ __launch_bounds__(256, 2)
void xg_gemm_kernel(const float* __restrict__ X,
                    const float* __restrict__ Wf, const float* __restrict__ Wb,
                    const float* __restrict__ bihf, const float* __restrict__ bhhf,
                    const float* __restrict__ bihb, const float* __restrict__ bhhb) {
    __shared__ float As[8][128];
    __shared__ float Bs[8][128];

    const int tid = threadIdx.x;
    const int m0 = blockIdx.y * 128;
    const int n0 = blockIdx.x * 128;
    const int d = n0 >> 12;                // 0 fwd, 1 bwd  (4096 % 128 == 0)
    const int gbase = n0 & (G4 - 1);
    const float* Wmat = d ? Wb : Wf;

    const int ty = tid >> 4;               // 0..15
    const int tx = tid & 15;               // 0..15

    const int lrow = tid >> 1;             // 0..127 (loader row)
    const int lk4 = (tid & 1) * 4;         // 0 or 4 (loader k offset)

    float acc[8][8];
#pragma unroll
    for (int i = 0; i < 8; i++)
#pragma unroll
        for (int j = 0; j < 8; j++) acc[i][j] = 0.f;

    for (int k0 = 0; k0 < I; k0 += 8) {
        {
            float4 a = *(const float4*)&X[(size_t)(m0 + lrow) * I + k0 + lk4];
            As[lk4 + 0][lrow] = a.x;
            As[lk4 + 1][lrow] = a.y;
            As[lk4 + 2][lrow] = a.z;
            As[lk4 + 3][lrow] = a.w;
            float4 b = *(const float4*)&Wmat[(size_t)(gbase + lrow) * I + k0 + lk4];
            Bs[lk4 + 0][lrow] = b.x;
            Bs[lk4 + 1][lrow] = b.y;
            Bs[lk4 + 2][lrow] = b.z;
            Bs[lk4 + 3][lrow] = b.w;
        }
        __syncthreads();
#pragma unroll
        for (int k = 0; k < 8; k++) {
            float4 a0 = *(const float4*)&As[k][ty * 8];
            float4 a1 = *(const float4*)&As[k][ty * 8 + 4];
            float4 b0 = *(const float4*)&Bs[k][tx * 8];
            float4 b1 = *(const float4*)&Bs[k][tx * 8 + 4];
            float av[8] = {a0.x, a0.y, a0.z, a0.w, a1.x, a1.y, a1.z, a1.w};
            float bv[8] = {b0.x, b0.y, b0.z, b0.w, b1.x, b1.y, b1.z, b1.w};
#pragma unroll
            for (int i = 0; i < 8; i++)
#pragma unroll
                for (int j = 0; j < 8; j++) acc[i][j] += av[i] * bv[j];
        }
        __syncthreads();
    }

    const float* bih = d ? bihb : bihf;
    const float* bhh = d ? bhhb : bhhf;
    float bias[8];
#pragma unroll
    for (int j = 0; j < 8; j++) {
        int g = gbase + tx * 8 + j;
        bias[j] = bih[g] + bhh[g];
    }
    float* outbase = g_xg + (size_t)d * M_ALL * G4;
#pragma unroll
    for (int i = 0; i < 8; i++) {
        int m = m0 + ty * 8 + i;
        float* row = outbase + (size_t)m * G4 + gbase + tx * 8;
#pragma unroll
        for (int j = 0; j < 8; j++) row[j] = acc[i][j] + bias[j];
    }
}

// ---------------------------------------------------------------------------
// Kernel: one LSTM timestep, both directions.
// Grid: 128 CTAs = 2 dirs x 64 slices of 16 hidden units (64 gate rows).
// Each CTA: gates[64 rows x 32 batch] = Whh_slice @ h_prev^T (K=1024),
// then + xg, then cell update. h written into d_out (serves as history).
// ---------------------------------------------------------------------------
__global__ __launch_bounds__(256)
void lstm_step_kernel(int t,
                      const float* __restrict__ Whhf,
                      const float* __restrict__ Whhb,
                      const float* __restrict__ h0f,
                      const float* __restrict__ h0b,
                      float* __restrict__ out) {
    __shared__ float Ws[64][36];   // padded for conflict-free float4 LDS
    __shared__ float Hs[32][36];
    __shared__ float Gs[64][33];

    const int tid = threadIdx.x;
    const int d = blockIdx.x >> 6;     // 0 fwd, 1 bwd
    const int s = blockIdx.x & 63;
    const int j0 = s * 16;             // hidden-unit slice base

    const int t_eff = d ? (T - 1 - t) : t;
    const float* Whh = d ? Whhb : Whhf;

    const float* hp;
    int hstride;
    if (t == 0) {
        hp = d ? h0b : h0f;
        hstride = H;
    } else {
        int tp = d ? (t_eff + 1) : (t_eff - 1);
        hp = out + (size_t)tp * B * OUT_COLS + (size_t)d * H;
        hstride = OUT_COLS;
    }

    const int c = tid & 31;                 // batch column
    const int rbase = (tid >> 5) * 8;       // 8 gate rows per thread

    float acc[8] = {0, 0, 0, 0, 0, 0, 0, 0};

    for (int k0 = 0; k0 < H; k0 += 32) {
        // W tile: 64 rows x 32 k = 512 float4, 2 per thread
#pragma unroll
        for (int rep = 0; rep < 2; rep++) {
            int f = tid + rep * 256;
            int lr = f >> 3;
            int kq = (f & 7) * 4;
            int grow = (lr >> 4) * H + j0 + (lr & 15);   // gate-row -> W row
            float4 w = *(const float4*)&Whh[(size_t)grow * H + k0 + kq];
            *(float4*)&Ws[lr][kq] = w;
        }
        // H tile: 32 rows x 32 k = 256 float4, 1 per thread
        {
            int cc = tid >> 3;
            int kq = (tid & 7) * 4;
            float4 h = *(const float4*)&hp[(size_t)cc * hstride + k0 + kq];
            *(float4*)&Hs[cc][kq] = h;
        }
        __syncthreads();
#pragma unroll
        for (int kq = 0; kq < 32; kq += 4) {
            float4 hv = *(const float4*)&Hs[c][kq];
#pragma unroll
            for (int i = 0; i < 8; i++) {
                float4 wv = *(const float4*)&Ws[rbase + i][kq];
                acc[i] += hv.x * wv.x;
                acc[i] += hv.y * wv.y;
                acc[i] += hv.z * wv.z;
                acc[i] += hv.w * wv.w;
            }
        }
        __syncthreads();
    }

    // add precomputed input projection, stage gates in smem
    {
        const float* xg = g_xg + (size_t)d * M_ALL * G4
                               + (size_t)(t_eff * B + c) * G4;
#pragma unroll
        for (int i = 0; i < 8; i++) {
            int lr = rbase + i;
            int grow = (lr >> 4) * H + j0 + (lr & 15);
            Gs[lr][c] = acc[i] + xg[grow];
        }
    }
    __syncthreads();

    // pointwise cell update: 16 hidden units x 32 batch = 512 items
#pragma unroll
    for (int rep = 0; rep < 2; rep++) {
        int id = tid + rep * 256;
        int b = id & 31;
        int jj = id >> 5;                    // 0..15
        float ig = Gs[jj][b];
        float fg = Gs[16 + jj][b];
        float gg = Gs[32 + jj][b];
        float og = Gs[48 + jj][b];
        ig = 1.f / (1.f + expf(-ig));
        fg = 1.f / (1.f + expf(-fg));
        og = 1.f / (1.f + expf(-og));
        gg = tanhf(gg);
        size_t cidx = (size_t)d * B * H + (size_t)b * H + j0 + jj;
        float cn = fg * g_c[cidx] + ig * gg;
        g_c[cidx] = cn;
        float hn = og * tanhf(cn);
        out[(size_t)t_eff * B * OUT_COLS + (size_t)b * OUT_COLS
            + (size_t)d * H + j0 + jj] = hn;
    }
}

// ---------------------------------------------------------------------------
// Kernel: finalize tail outputs (hf, cf, hb, cb) after out[]
// ---------------------------------------------------------------------------
__global__ void finalize_kernel(float* __restrict__ out) {
    int i = blockIdx.x * blockDim.x + threadIdx.x;
    if (i >= B * H) return;
    int b = i >> 10;       // / H
    int j = i & (H - 1);
    float* tail = out + OUT_MAIN;
    tail[i]             = out[(size_t)(T - 1) * B * OUT_COLS + (size_t)b * OUT_COLS + j]; // hf
    tail[B * H + i]     = g_c[i];                                                          // cf
    tail[2 * B * H + i] = out[(size_t)b * OUT_COLS + H + j];                               // hb
    tail[3 * B * H + i] = g_c[B * H + i];                                                  // cb
}

// ---------------------------------------------------------------------------
extern "C" void kernel_launch(void* const* d_in, const int* in_sizes, int n_in,
                              void* d_out, int out_size) {
    const float* x    = (const float*)d_in[0];
    const float* h0f  = (const float*)d_in[1];
    const float* c0f  = (const float*)d_in[2];
    const float* h0b  = (const float*)d_in[3];
    const float* c0b  = (const float*)d_in[4];
    const float* Wihf = (const float*)d_in[5];
    const float* Whhf = (const float*)d_in[6];
    const float* bihf = (const float*)d_in[7];
    const float* bhhf = (const float*)d_in[8];
    const float* Wihb = (const float*)d_in[9];
    const float* Whhb = (const float*)d_in[10];
    const float* bihb = (const float*)d_in[11];
    const float* bhhb = (const float*)d_in[12];
    float* out = (float*)d_out;

    init_c_kernel<<<(B * H + 255) / 256, 256>>>(c0f, c0b);

    dim3 grid_xg(8192 / 128, M_ALL / 128);   // (64, 128)
    xg_gemm_kernel<<<grid_xg, 256>>>(x, Wihf, Wihb, bihf, bhhf, bihb, bhhb);

    for (int t = 0; t < T; t++)
        lstm_step_kernel<<<128, 256>>>(t, Whhf, Whhb, h0f, h0b, out);

    finalize_kernel<<<(B * H + 255) / 256, 256>>>(out);
}

// round 2
// speedup vs baseline: 1.6807x; 1.6807x over previous
#include <cuda_runtime.h>
#include <math.h>

// ---------------------------------------------------------------------------
// Bidirectional LSTM: T=512, B=32, I=1024, H=1024.
// Round 2: recurrence via mma.sync tf32 tensor cores.
//   K_init : copy c0 -> g_c
//   K_wprep: pre-round Whh (both dirs) to tf32 into g_Wr
//   K_xg   : fp32 SGEMM xg = x@Wih^T + bih + bhh (both dirs)
//   K_step : (x512) gates = xg[t] + h_{t-1} @ Whh^T via m16n8k8.tf32 mma
//   K_fin  : tail hf/cf/hb/cb
// ---------------------------------------------------------------------------

namespace {
constexpr int T = 512;
constexpr int B = 32;
constexpr int I = 1024;
constexpr int H = 1024;
constexpr int G4 = 4 * H;          // 4096
constexpr int OUT_COLS = 2 * H;    // 2048
constexpr int M_ALL = T * B;       // 16384
constexpr long long OUT_MAIN = (long long)T * B * OUT_COLS;
}

__device__ float g_xg[2LL * M_ALL * G4];   // [dir][t*B+b][4H]
__device__ float g_c[2 * B * H];           // cell state per direction
__device__ float g_Wr[2LL * G4 * H];       // tf32-rounded Whh [dir][4096][1024]

__device__ __forceinline__ float tf32r(float x) {
    unsigned r;
    asm("cvt.rna.tf32.f32 %0, %1;" : "=r"(r) : "f"(x));
    return __uint_as_float(r);
}

__device__ __forceinline__ void mma_tf32(float* d, const unsigned* a,
                                         unsigned b0, unsigned b1) {
    asm volatile(
        "mma.sync.aligned.m16n8k8.row.col.f32.tf32.tf32.f32 "
        "{%0,%1,%2,%3}, {%4,%5,%6,%7}, {%8,%9}, {%0,%1,%2,%3};"
        : "+f"(d[0]), "+f"(d[1]), "+f"(d[2]), "+f"(d[3])
        : "r"(a[0]), "r"(a[1]), "r"(a[2]), "r"(a[3]), "r"(b0), "r"(b1));
}

// ---------------------------------------------------------------------------
__global__ void init_c_kernel(const float* __restrict__ c0f,
                              const float* __restrict__ c0b) {
    int i = blockIdx.x * blockDim.x + threadIdx.x;
    if (i < B * H) {
        g_c[i]         = c0f[i];
        g_c[B * H + i] = c0b[i];
    }
}

__global__ void wprep_kernel(const float* __restrict__ Whhf,
                             const float* __restrict__ Whhb) {
    long long i = (long long)blockIdx.x * blockDim.x + threadIdx.x;
    const long long N = (long long)G4 * H;
    if (i < N) {
        g_Wr[i]     = tf32r(Whhf[i]);
        g_Wr[N + i] = tf32r(Whhb[i]);
    }
}

// ---------------------------------------------------------------------------
// fp32 SGEMM for xg (unchanged from round 1)
// ---------------------------------------------------------------------------
__global__ __launch_bounds__(256, 2)
void xg_gemm_kernel(const float* __restrict__ X,
                    const float* __restrict__ Wf, const float* __restrict__ Wb,
                    const float* __restrict__ bihf, const float* __restrict__ bhhf,
                    const float* __restrict__ bihb, const float* __restrict__ bhhb) {
    __shared__ float As[8][128];
    __shared__ float Bs[8][128];

    const int tid = threadIdx.x;
    const int m0 = blockIdx.y * 128;
    const int n0 = blockIdx.x * 128;
    const int d = n0 >> 12;
    const int gbase = n0 & (G4 - 1);
    const float* Wmat = d ? Wb : Wf;

    const int ty = tid >> 4;
    const int tx = tid & 15;
    const int lrow = tid >> 1;
    const int lk4 = (tid & 1) * 4;

    float acc[8][8];
#pragma unroll
    for (int i = 0; i < 8; i++)
#pragma unroll
        for (int j = 0; j < 8; j++) acc[i][j] = 0.f;

    for (int k0 = 0; k0 < I; k0 += 8) {
        {
            float4 a = *(const float4*)&X[(size_t)(m0 + lrow) * I + k0 + lk4];
            As[lk4 + 0][lrow] = a.x;
            As[lk4 + 1][lrow] = a.y;
            As[lk4 + 2][lrow] = a.z;
            As[lk4 + 3][lrow] = a.w;
            float4 b = *(const float4*)&Wmat[(size_t)(gbase + lrow) * I + k0 + lk4];
            Bs[lk4 + 0][lrow] = b.x;
            Bs[lk4 + 1][lrow] = b.y;
            Bs[lk4 + 2][lrow] = b.z;
            Bs[lk4 + 3][lrow] = b.w;
        }
        __syncthreads();
#pragma unroll
        for (int k = 0; k < 8; k++) {
            float4 a0 = *(const float4*)&As[k][ty * 8];
            float4 a1 = *(const float4*)&As[k][ty * 8 + 4];
            float4 b0 = *(const float4*)&Bs[k][tx * 8];
            float4 b1 = *(const float4*)&Bs[k][tx * 8 + 4];
            float av[8] = {a0.x, a0.y, a0.z, a0.w, a1.x, a1.y, a1.z, a1.w};
            float bv[8] = {b0.x, b0.y, b0.z, b0.w, b1.x, b1.y, b1.z, b1.w};
#pragma unroll
            for (int i = 0; i < 8; i++)
#pragma unroll
                for (int j = 0; j < 8; j++) acc[i][j] += av[i] * bv[j];
        }
        __syncthreads();
    }

    const float* bih = d ? bihb : bihf;
    const float* bhh = d ? bhhb : bhhf;
    float bias[8];
#pragma unroll
    for (int j = 0; j < 8; j++) {
        int g = gbase + tx * 8 + j;
        bias[j] = bih[g] + bhh[g];
    }
    float* outbase = g_xg + (size_t)d * M_ALL * G4;
#pragma unroll
    for (int i = 0; i < 8; i++) {
        int m = m0 + ty * 8 + i;
        float* row = outbase + (size_t)m * G4 + gbase + tx * 8;
#pragma unroll
        for (int j = 0; j < 8; j++) row[j] = acc[i][j] + bias[j];
    }
}

// ---------------------------------------------------------------------------
// One LSTM timestep, both directions, tensor-core recurrence.
// Grid: 128 CTAs = 2 dirs x 64 slices of 16 hidden units (64 gate rows:
// rows [0,16)=i, [16,32)=f, [32,48)=g, [48,64)=o for units j0..j0+15).
// 8 warps, warp (mw = w&3, nw = w>>2) computes m16 (gate mw) x n16
// (batch nw*16..+15) with K=1024 in double-buffered 32-wide smem tiles.
// ---------------------------------------------------------------------------
__global__ __launch_bounds__(256)
void lstm_step_mma(int t,
                   const float* __restrict__ h0f,
                   const float* __restrict__ h0b,
                   float* __restrict__ out) {
    __shared__ float Ws[2][64][36];   // pitch 36 -> conflict-free frag loads
    __shared__ float Hs[2][32][36];
    __shared__ float Gs[4][16][33];   // [gate][unit][batch]

    const int tid = threadIdx.x;
    const int d = blockIdx.x >> 6;
    const int s = blockIdx.x & 63;
    const int j0 = s * 16;
    const int t_eff = d ? (T - 1 - t) : t;

    const float* hp;
    int hstride;
    if (t == 0) {
        hp = d ? h0b : h0f;
        hstride = H;
    } else {
        int tp = d ? (t_eff + 1) : (t_eff - 1);
        hp = out + (size_t)tp * B * OUT_COLS + (size_t)d * H;
        hstride = OUT_COLS;
    }

    // ---- loader setup ----
    const int kq = (tid & 7) * 4;               // k offset within tile (float4)
    const int wlr0 = tid >> 3;                  // W rows 0..31 (rep0), +32 (rep1)
    const int wlr1 = wlr0 + 32;
    const int hb = tid >> 3;                    // h batch row 0..31
    const float* Wbase = g_Wr + (size_t)d * G4 * H;
    const int grow0 = (wlr0 >> 4) * H + j0 + (wlr0 & 15);
    const int grow1 = (wlr1 >> 4) * H + j0 + (wlr1 & 15);
    const float* wp0 = Wbase + (size_t)grow0 * H + kq;
    const float* wp1 = Wbase + (size_t)grow1 * H + kq;
    const float* hpp = hp + (size_t)hb * hstride + kq;

    // ---- mma setup ----
    const int warp = tid >> 5;
    const int lane = tid & 31;
    const int mw = warp & 3;                    // gate type / m-tile
    const int nw = warp >> 2;                   // batch half
    const int lrq = lane >> 2;
    const int lc = lane & 3;
    const int mrow = mw * 16;
    const int nrow0 = nw * 16;

    float acc0[4] = {0, 0, 0, 0};
    float acc1[4] = {0, 0, 0, 0};

    // prologue: stage tile 0
    {
        float4 w0 = *(const float4*)wp0;
        float4 w1 = *(const float4*)wp1;
        float4 hv = *(const float4*)hpp;
        *(float4*)&Ws[0][wlr0][kq] = w0;
        *(float4*)&Ws[0][wlr1][kq] = w1;
        Hs[0][hb][kq + 0] = tf32r(hv.x);
        Hs[0][hb][kq + 1] = tf32r(hv.y);
        Hs[0][hb][kq + 2] = tf32r(hv.z);
        Hs[0][hb][kq + 3] = tf32r(hv.w);
    }
    __syncthreads();

    for (int kt = 0; kt < 32; kt++) {
        const int cur = kt & 1;
        float4 w0, w1, hv;
        if (kt < 31) {
            int off = (kt + 1) * 32;
            w0 = *(const float4*)(wp0 + off);
            w1 = *(const float4*)(wp1 + off);
            hv = *(const float4*)(hpp + off);
        }
#pragma unroll
        for (int k8 = 0; k8 < 4; k8++) {
            const int c0 = k8 * 8 + lc;
            unsigned a[4];
            a[0] = __float_as_uint(Ws[cur][mrow + lrq][c0]);
            a[1] = __float_as_uint(Ws[cur][mrow + lrq + 8][c0]);
            a[2] = __float_as_uint(Ws[cur][mrow + lrq][c0 + 4]);
            a[3] = __float_as_uint(Ws[cur][mrow + lrq + 8][c0 + 4]);
            unsigned b0 = __float_as_uint(Hs[cur][nrow0 + lrq][c0]);
            unsigned b1 = __float_as_uint(Hs[cur][nrow0 + lrq][c0 + 4]);
            mma_tf32(acc0, a, b0, b1);
            unsigned b2 = __float_as_uint(Hs[cur][nrow0 + 8 + lrq][c0]);
            unsigned b3 = __float_as_uint(Hs[cur][nrow0 + 8 + lrq][c0 + 4]);
            mma_tf32(acc1, a, b2, b3);
        }
        if (kt < 31) {
            const int nxt = cur ^ 1;
            *(float4*)&Ws[nxt][wlr0][kq] = w0;
            *(float4*)&Ws[nxt][wlr1][kq] = w1;
            Hs[nxt][hb][kq + 0] = tf32r(hv.x);
            Hs[nxt][hb][kq + 1] = tf32r(hv.y);
            Hs[nxt][hb][kq + 2] = tf32r(hv.z);
            Hs[nxt][hb][kq + 3] = tf32r(hv.w);
        }
        __syncthreads();
    }

    // ---- stage gate pre-activations to smem ----
    {
        const int r = lrq;
        const int cbase = nrow0 + lc * 2;
        Gs[mw][r][cbase + 0]     = acc0[0];
        Gs[mw][r][cbase + 1]     = acc0[1];
        Gs[mw][r + 8][cbase + 0] = acc0[2];
        Gs[mw][r + 8][cbase + 1] = acc0[3];
        Gs[mw][r][cbase + 8]     = acc1[0];
        Gs[mw][r][cbase + 9]     = acc1[1];
        Gs[mw][r + 8][cbase + 8] = acc1[2];
        Gs[mw][r + 8][cbase + 9] = acc1[3];
    }
    __syncthreads();

    // ---- pointwise cell update: 16 units x 32 batch ----
#pragma unroll
    for (int rep = 0; rep < 2; rep++) {
        int id = tid + rep * 256;
        int b = id & 31;
        int jj = id >> 5;     // 0..15
        const float* xg = g_xg + (size_t)d * M_ALL * G4
                               + (size_t)(t_eff * B + b) * G4 + j0 + jj;
        float ig = Gs[0][jj][b] + xg[0];
        float fg = Gs[1][jj][b] + xg[H];
        float gg = Gs[2][jj][b] + xg[2 * H];
        float og = Gs[3][jj][b] + xg[3 * H];
        ig = 1.f / (1.f + expf(-ig));
        fg = 1.f / (1.f + expf(-fg));
        og = 1.f / (1.f + expf(-og));
        gg = tanhf(gg);
        size_t cidx = (size_t)d * B * H + (size_t)b * H + j0 + jj;
        float cn = fg * g_c[cidx] + ig * gg;
        g_c[cidx] = cn;
        float hn = og * tanhf(cn);
        out[(size_t)t_eff * B * OUT_COLS + (size_t)b * OUT_COLS
            + (size_t)d * H + j0 + jj] = hn;
    }
}

// ---------------------------------------------------------------------------
__global__ void finalize_kernel(float* __restrict__ out) {
    int i = blockIdx.x * blockDim.x + threadIdx.x;
    if (i >= B * H) return;
    int b = i >> 10;
    int j = i & (H - 1);
    float* tail = out + OUT_MAIN;
    tail[i]             = out[(size_t)(T - 1) * B * OUT_COLS + (size_t)b * OUT_COLS + j];
    tail[B * H + i]     = g_c[i];
    tail[2 * B * H + i] = out[(size_t)b * OUT_COLS + H + j];
    tail[3 * B * H + i] = g_c[B * H + i];
}

// ---------------------------------------------------------------------------
extern "C" void kernel_launch(void* const* d_in, const int* in_sizes, int n_in,
                              void* d_out, int out_size) {
    const float* x    = (const float*)d_in[0];
    const float* h0f  = (const float*)d_in[1];
    const float* c0f  = (const float*)d_in[2];
    const float* h0b  = (const float*)d_in[3];
    const float* c0b  = (const float*)d_in[4];
    const float* Wihf = (const float*)d_in[5];
    const float* Whhf = (const float*)d_in[6];
    const float* bihf = (const float*)d_in[7];
    const float* bhhf = (const float*)d_in[8];
    const float* Wihb = (const float*)d_in[9];
    const float* Whhb = (const float*)d_in[10];
    const float* bihb = (const float*)d_in[11];
    const float* bhhb = (const float*)d_in[12];
    float* out = (float*)d_out;

    init_c_kernel<<<(B * H + 255) / 256, 256>>>(c0f, c0b);
    wprep_kernel<<<(G4 * H + 255) / 256, 256>>>(Whhf, Whhb);

    dim3 grid_xg(8192 / 128, M_ALL / 128);
    xg_gemm_kernel<<<grid_xg, 256>>>(x, Wihf, Wihb, bihf, bhhf, bihb, bhhb);

    for (int t = 0; t < T; t++)
        lstm_step_mma<<<128, 256>>>(t, h0f, h0b, out);

    finalize_kernel<<<(B * H + 255) / 256, 256>>>(out);
}

// round 3
// speedup vs baseline: 2.8418x; 1.6909x over previous
#include <cuda_runtime.h>
#include <cuda_fp16.h>
#include <math.h>

// ---------------------------------------------------------------------------
// Bidirectional LSTM: T=512, B=32, I=1024, H=1024.
// Round 3: single persistent kernel for the recurrence.
//   - Whh prepacked to fp16 mma fragments in SMEM, resident across all 512 steps
//   - per-direction software grid barrier between steps (all CTAs resident)
//   - h passed step-to-step via parity-double-buffered fp16 staging buffer
//   - c held in registers for the whole sequence
//   xg = x@Wih^T + biases stays fp32 SGEMM (separate kernel).
// ---------------------------------------------------------------------------

namespace {
constexpr int T = 512;
constexpr int B = 32;
constexpr int I = 1024;
constexpr int H = 1024;
constexpr int G4 = 4 * H;          // 4096
constexpr int OUT_COLS = 2 * H;    // 2048
constexpr int M_ALL = T * B;       // 16384
constexpr long long OUT_MAIN = (long long)T * B * OUT_COLS;

constexpr int CTAS = 128;          // 2 dirs x 64 unit-slices (16 units each)
constexpr int THREADS = 256;
constexpr int CTAS_PER_DIR = 64;

constexpr int HS_PITCH = 1032;     // halves; 516 words -> conflict-free B loads
constexpr int SMEM_W  = 4 * 64 * 32 * 16;           // 131072 B (uint4 frags)
constexpr int SMEM_HS = 32 * HS_PITCH * 2;          // 66048 B
constexpr int SMEM_GS = 4 * 16 * 33 * 4;            // 8448 B
constexpr int SMEM_BYTES = SMEM_W + SMEM_HS + SMEM_GS;   // 205568
}

__device__ float g_xg[2LL * M_ALL * G4];        // [dir][t*B+b][4H]
__device__ float g_c[2 * B * H];                // final cell state (for tail)
__device__ __half g_hstage[2][2][B][H];         // [parity][dir][b][k]
__device__ unsigned g_bar[2];                   // per-direction barrier counters

__device__ __forceinline__ void mma_fp16(float* d, const uint4& a,
                                         unsigned b0, unsigned b1) {
    asm volatile(
        "mma.sync.aligned.m16n8k16.row.col.f32.f16.f16.f32 "
        "{%0,%1,%2,%3}, {%4,%5,%6,%7}, {%8,%9}, {%0,%1,%2,%3};"
        : "+f"(d[0]), "+f"(d[1]), "+f"(d[2]), "+f"(d[3])
        : "r"(a.x), "r"(a.y), "r"(a.z), "r"(a.w), "r"(b0), "r"(b1));
}

// ---------------------------------------------------------------------------
__global__ void init_kernel(const float* __restrict__ h0f,
                            const float* __restrict__ h0b) {
    int i = blockIdx.x * blockDim.x + threadIdx.x;
    if (i == 0) { g_bar[0] = 0; g_bar[1] = 0; }
    if (i < B * H) {
        int b = i >> 10;
        int k = i & 1023;
        g_hstage[0][0][b][k] = __float2half(h0f[i]);
        g_hstage[0][1][b][k] = __float2half(h0b[i]);
    }
}

// ---------------------------------------------------------------------------
// fp32 SGEMM for xg (unchanged)
// ---------------------------------------------------------------------------
__global__ __launch_bounds__(256, 2)
void xg_gemm_kernel(const float* __restrict__ X,
                    const float* __restrict__ Wf, const float* __restrict__ Wb,
                    const float* __restrict__ bihf, const float* __restrict__ bhhf,
                    const float* __restrict__ bihb, const float* __restrict__ bhhb) {
    __shared__ float As[8][128];
    __shared__ float Bs[8][128];

    const int tid = threadIdx.x;
    const int m0 = blockIdx.y * 128;
    const int n0 = blockIdx.x * 128;
    const int d = n0 >> 12;
    const int gbase = n0 & (G4 - 1);
    const float* Wmat = d ? Wb : Wf;

    const int ty = tid >> 4;
    const int tx = tid & 15;
    const int lrow = tid >> 1;
    const int lk4 = (tid & 1) * 4;

    float acc[8][8];
#pragma unroll
    for (int i = 0; i < 8; i++)
#pragma unroll
        for (int j = 0; j < 8; j++) acc[i][j] = 0.f;

    for (int k0 = 0; k0 < I; k0 += 8) {
        {
            float4 a = *(const float4*)&X[(size_t)(m0 + lrow) * I + k0 + lk4];
            As[lk4 + 0][lrow] = a.x;
            As[lk4 + 1][lrow] = a.y;
            As[lk4 + 2][lrow] = a.z;
            As[lk4 + 3][lrow] = a.w;
            float4 b = *(const float4*)&Wmat[(size_t)(gbase + lrow) * I + k0 + lk4];
            Bs[lk4 + 0][lrow] = b.x;
            Bs[lk4 + 1][lrow] = b.y;
            Bs[lk4 + 2][lrow] = b.z;
            Bs[lk4 + 3][lrow] = b.w;
        }
        __syncthreads();
#pragma unroll
        for (int k = 0; k < 8; k++) {
            float4 a0 = *(const float4*)&As[k][ty * 8];
            float4 a1 = *(const float4*)&As[k][ty * 8 + 4];
            float4 b0 = *(const float4*)&Bs[k][tx * 8];
            float4 b1 = *(const float4*)&Bs[k][tx * 8 + 4];
            float av[8] = {a0.x, a0.y, a0.z, a0.w, a1.x, a1.y, a1.z, a1.w};
            float bv[8] = {b0.x, b0.y, b0.z, b0.w, b1.x, b1.y, b1.z, b1.w};
#pragma unroll
            for (int i = 0; i < 8; i++)
#pragma unroll
                for (int j = 0; j < 8; j++) acc[i][j] += av[i] * bv[j];
        }
        __syncthreads();
    }

    const float* bih = d ? bihb : bihf;
    const float* bhh = d ? bhhb : bhhf;
    float bias[8];
#pragma unroll
    for (int j = 0; j < 8; j++) {
        int g = gbase + tx * 8 + j;
        bias[j] = bih[g] + bhh[g];
    }
    float* outbase = g_xg + (size_t)d * M_ALL * G4;
#pragma unroll
    for (int i = 0; i < 8; i++) {
        int m = m0 + ty * 8 + i;
        float* row = outbase + (size_t)m * G4 + gbase + tx * 8;
#pragma unroll
        for (int j = 0; j < 8; j++) row[j] = acc[i][j] + bias[j];
    }
}

// ---------------------------------------------------------------------------
// Persistent recurrence kernel. grid=128 (1 CTA/SM guaranteed by smem size),
// block=256. CTA = (dir, 16-unit slice). All 512 timesteps in one launch.
// ---------------------------------------------------------------------------
__global__ __launch_bounds__(THREADS, 1)
void lstm_persistent(const float* __restrict__ Whhf,
                     const float* __restrict__ Whhb,
                     const float* __restrict__ c0f,
                     const float* __restrict__ c0b,
                     float* __restrict__ out) {
    extern __shared__ char smem[];
    uint4*  Wf = (uint4*)smem;                       // [4 mw][64 kc][32 lane]
    __half* Hs = (__half*)(smem + SMEM_W);           // [32][HS_PITCH]
    float*  Gs = (float*)(smem + SMEM_W + SMEM_HS);  // [4*16][33]

    const int tid = threadIdx.x;
    const int d = blockIdx.x >> 6;
    const int s = blockIdx.x & 63;
    const int j0 = s * 16;
    const float* Whh = d ? Whhb : Whhf;

    // ---- prepack W slice into fp16 mma-fragment layout (once) ----
    for (int s0 = tid; s0 < 4 * 64 * 32; s0 += THREADS) {
        int l  = s0 & 31;
        int kc = (s0 >> 5) & 63;
        int mw = s0 >> 11;
        int r  = l >> 2;
        int t4 = l & 3;
        int row0 = mw * H + j0 + r;       // gate mw, unit j0+r
        int row1 = row0 + 8;
        int k0 = kc * 16 + 2 * t4;
        float2 f0 = *(const float2*)&Whh[(size_t)row0 * H + k0];
        float2 f1 = *(const float2*)&Whh[(size_t)row1 * H + k0];
        float2 f2 = *(const float2*)&Whh[(size_t)row0 * H + k0 + 8];
        float2 f3 = *(const float2*)&Whh[(size_t)row1 * H + k0 + 8];
        __half2 h0 = __float22half2_rn(f0);
        __half2 h1 = __float22half2_rn(f1);
        __half2 h2 = __float22half2_rn(f2);
        __half2 h3 = __float22half2_rn(f3);
        uint4 v;
        v.x = *(unsigned*)&h0;
        v.y = *(unsigned*)&h1;
        v.z = *(unsigned*)&h2;
        v.w = *(unsigned*)&h3;
        Wf[s0] = v;
    }

    // ---- cell state in registers: id = tid + rep*256 -> (jj = id&15, b = id>>4)
    float c_reg[2];
#pragma unroll
    for (int rep = 0; rep < 2; rep++) {
        int id = tid + rep * 256;
        int jj = id & 15;
        int b = id >> 4;
        c_reg[rep] = (d ? c0b : c0f)[b * H + j0 + jj];
    }

    // ---- warp/mma constants ----
    const int warp = tid >> 5;
    const int lane = tid & 31;
    const int mw = warp & 3;            // gate (m16 tile)
    const int nw = warp >> 2;           // batch half (n16)
    const int gID = lane >> 2;
    const int t4 = lane & 3;
    const uint4* wfrag = Wf + mw * 2048 + lane;
    const __half* hp0 = &Hs[(nw * 16 + gID) * HS_PITCH + 2 * t4];
    const __half* hp1 = hp0 + 8 * HS_PITCH;

    const size_t xg_dir = (size_t)d * M_ALL * G4;
    volatile unsigned* barp = &g_bar[d];

    for (int t = 0; t < T; t++) {
        const int p = t & 1;
        const int t_eff = d ? (T - 1 - t) : t;

        // ---- stage h (fp16) into Hs ----
        const uint4* src = (const uint4*)&g_hstage[p][d][0][0];
#pragma unroll
        for (int i = 0; i < 16; i++) {
            int s1 = tid + i * 256;      // 0..4095
            int b = s1 >> 7;
            int q = s1 & 127;
            uint4 v = __ldcg(src + s1);
            *(uint4*)&Hs[b * HS_PITCH + q * 8] = v;
        }
        __syncthreads();

        // ---- K=1024 mma loop, sync-free ----
        float acc0[4] = {0.f, 0.f, 0.f, 0.f};
        float acc1[4] = {0.f, 0.f, 0.f, 0.f};
#pragma unroll 8
        for (int kc = 0; kc < 64; kc++) {
            uint4 a = wfrag[kc * 32];
            unsigned b00 = *(const unsigned*)(hp0 + kc * 16);
            unsigned b01 = *(const unsigned*)(hp0 + kc * 16 + 8);
            unsigned b10 = *(const unsigned*)(hp1 + kc * 16);
            unsigned b11 = *(const unsigned*)(hp1 + kc * 16 + 8);
            mma_fp16(acc0, a, b00, b01);
            mma_fp16(acc1, a, b10, b11);
        }

        // ---- stage gate pre-activations ----
        {
            int row = mw * 16 + gID;
            int cb = nw * 16 + 2 * t4;
            Gs[row * 33 + cb]           = acc0[0];
            Gs[row * 33 + cb + 1]       = acc0[1];
            Gs[(row + 8) * 33 + cb]     = acc0[2];
            Gs[(row + 8) * 33 + cb + 1] = acc0[3];
            Gs[row * 33 + cb + 8]       = acc1[0];
            Gs[row * 33 + cb + 9]       = acc1[1];
            Gs[(row + 8) * 33 + cb + 8] = acc1[2];
            Gs[(row + 8) * 33 + cb + 9] = acc1[3];
        }
        __syncthreads();

        // ---- pointwise cell update ----
#pragma unroll
        for (int rep = 0; rep < 2; rep++) {
            int id = tid + rep * 256;
            int jj = id & 15;
            int b = id >> 4;
            const float* xg = g_xg + xg_dir
                            + (size_t)(t_eff * B + b) * G4 + j0 + jj;
            float ig = Gs[(0  + jj) * 33 + b] + xg[0];
            float fg = Gs[(16 + jj) * 33 + b] + xg[H];
            float gg = Gs[(32 + jj) * 33 + b] + xg[2 * H];
            float og = Gs[(48 + jj) * 33 + b] + xg[3 * H];
            ig = 1.f / (1.f + expf(-ig));
            fg = 1.f / (1.f + expf(-fg));
            og = 1.f / (1.f + expf(-og));
            gg = tanhf(gg);
            float cn = fg * c_reg[rep] + ig * gg;
            c_reg[rep] = cn;
            float hn = og * tanhf(cn);
            out[(size_t)t_eff * B * OUT_COLS + (size_t)b * OUT_COLS
                + (size_t)d * H + j0 + jj] = hn;
            g_hstage[p ^ 1][d][b][j0 + jj] = __float2half(hn);
        }

        // ---- per-direction grid barrier ----
        if (t + 1 < T) {
            __syncthreads();
            if (tid == 0) {
                __threadfence();
                atomicAdd(&g_bar[d], 1u);
                unsigned tgt = (unsigned)CTAS_PER_DIR * (t + 1);
                while (*barp < tgt) { }
                __threadfence();
            }
            __syncthreads();
        }
    }

    // ---- dump final c for the tail writer ----
#pragma unroll
    for (int rep = 0; rep < 2; rep++) {
        int id = tid + rep * 256;
        int jj = id & 15;
        int b = id >> 4;
        g_c[(size_t)d * B * H + (size_t)b * H + j0 + jj] = c_reg[rep];
    }
}

// ---------------------------------------------------------------------------
__global__ void finalize_kernel(float* __restrict__ out) {
    int i = blockIdx.x * blockDim.x + threadIdx.x;
    if (i >= B * H) return;
    int b = i >> 10;
    int j = i & (H - 1);
    float* tail = out + OUT_MAIN;
    tail[i]             = out[(size_t)(T - 1) * B * OUT_COLS + (size_t)b * OUT_COLS + j];
    tail[B * H + i]     = g_c[i];
    tail[2 * B * H + i] = out[(size_t)b * OUT_COLS + H + j];
    tail[3 * B * H + i] = g_c[B * H + i];
}

// ---------------------------------------------------------------------------
extern "C" void kernel_launch(void* const* d_in, const int* in_sizes, int n_in,
                              void* d_out, int out_size) {
    const float* x    = (const float*)d_in[0];
    const float* h0f  = (const float*)d_in[1];
    const float* c0f  = (const float*)d_in[2];
    const float* h0b  = (const float*)d_in[3];
    const float* c0b  = (const float*)d_in[4];
    const float* Wihf = (const float*)d_in[5];
    const float* Whhf = (const float*)d_in[6];
    const float* bihf = (const float*)d_in[7];
    const float* bhhf = (const float*)d_in[8];
    const float* Wihb = (const float*)d_in[9];
    const float* Whhb = (const float*)d_in[10];
    const float* bihb = (const float*)d_in[11];
    const float* bhhb = (const float*)d_in[12];
    float* out = (float*)d_out;

    static int smem_set = 0;
    if (!smem_set) {
        cudaFuncSetAttribute(lstm_persistent,
                             cudaFuncAttributeMaxDynamicSharedMemorySize,
                             SMEM_BYTES);
        smem_set = 1;
    }

    init_kernel<<<(B * H + 255) / 256, 256>>>(h0f, h0b);

    dim3 grid_xg(8192 / 128, M_ALL / 128);
    xg_gemm_kernel<<<grid_xg, 256>>>(x, Wihf, Wihb, bihf, bhhf, bihb, bhhb);

    lstm_persistent<<<CTAS, THREADS, SMEM_BYTES>>>(Whhf, Whhb, c0f, c0b, out);

    finalize_kernel<<<(B * H + 255) / 256, 256>>>(out);
}

// round 4
// speedup vs baseline: 7.2004x; 2.5338x over previous
#include <cuda_runtime.h>
#include <cuda_fp16.h>
#include <math.h>

// ---------------------------------------------------------------------------
// Bidirectional LSTM: T=512, B=32, I=1024, H=1024.
// Round 4:
//   - xg GEMM moved to fp16 tensor cores (fragment-prepacked operands,
//     cp.async double-buffered, m64n64 warp tiles). xg stored fp16.
//   - persistent recurrence kernel keeps smem-resident fp16 Whh fragments;
//     adds xg register prefetch + fast activations.
// ---------------------------------------------------------------------------

namespace {
constexpr int T = 512;
constexpr int B = 32;
constexpr int I = 1024;
constexpr int H = 1024;
constexpr int G4 = 4 * H;          // 4096
constexpr int N_ALL = 2 * G4;      // 8192 (both dirs)
constexpr int OUT_COLS = 2 * H;    // 2048
constexpr int M_ALL = T * B;       // 16384
constexpr long long OUT_MAIN = (long long)T * B * OUT_COLS;

constexpr int CTAS = 128;
constexpr int THREADS = 256;
constexpr int CTAS_PER_DIR = 64;

constexpr int HS_PITCH = 1032;
constexpr int SMEM_W  = 4 * 64 * 32 * 16;           // 131072
constexpr int SMEM_HS = 32 * HS_PITCH * 2;          // 66048
constexpr int SMEM_GS = 4 * 16 * 33 * 4;            // 8448
constexpr int SMEM_BYTES = SMEM_W + SMEM_HS + SMEM_GS;

constexpr int KC = 64;             // number of k16 chunks (K=1024)
constexpr int M16 = M_ALL / 16;    // 1024
constexpr int N16 = N_ALL / 16;    // 512
}

__device__ __half g_xg[2LL * M_ALL * G4];       // [dir][m][4H] fp16
__device__ float g_c[2 * B * H];
__device__ __half g_hstage[2][2][B][H];
__device__ unsigned g_bar[2];
__device__ uint4 g_xa[(long long)M16 * KC * 32];   // a-fragments of x (32MB)
__device__ uint4 g_wb[(long long)N16 * KC * 32];   // b-fragments of Wih (16MB)

__device__ __forceinline__ void mma_fp16(float* d, const uint4& a,
                                         unsigned b0, unsigned b1) {
    asm volatile(
        "mma.sync.aligned.m16n8k16.row.col.f32.f16.f16.f32 "
        "{%0,%1,%2,%3}, {%4,%5,%6,%7}, {%8,%9}, {%0,%1,%2,%3};"
        : "+f"(d[0]), "+f"(d[1]), "+f"(d[2]), "+f"(d[3])
        : "r"(a.x), "r"(a.y), "r"(a.z), "r"(a.w), "r"(b0), "r"(b1));
}

__device__ __forceinline__ float sig_(float x) {
    return 1.f / (1.f + __expf(-x));
}
__device__ __forceinline__ float tanh_(float x) {
    float t = __expf(-2.f * fabsf(x));
    float r = (1.f - t) / (1.f + t);
    return x < 0.f ? -r : r;
}

#define CP_ASYNC16(smem_u32, gptr) \
    asm volatile("cp.async.cg.shared.global [%0], [%1], 16;" \
                 :: "r"(smem_u32), "l"(gptr))
#define CP_COMMIT() asm volatile("cp.async.commit_group;")
#define CP_WAIT1() asm volatile("cp.async.wait_group 1;")
#define CP_WAIT0() asm volatile("cp.async.wait_group 0;")

// ---------------------------------------------------------------------------
__global__ void init_kernel(const float* __restrict__ h0f,
                            const float* __restrict__ h0b) {
    int i = blockIdx.x * blockDim.x + threadIdx.x;
    if (i == 0) { g_bar[0] = 0; g_bar[1] = 0; }
    if (i < B * H) {
        int b = i >> 10;
        int k = i & 1023;
        g_hstage[0][0][b][k] = __float2half(h0f[i]);
        g_hstage[0][1][b][k] = __float2half(h0b[i]);
    }
}

// ---------------------------------------------------------------------------
// Prepack x -> a-fragments.  idx -> [m16][kc][lane]
// ---------------------------------------------------------------------------
__global__ void prepack_x(const float* __restrict__ x) {
    int idx = blockIdx.x * blockDim.x + threadIdx.x;
    if (idx >= M16 * KC * 32) return;
    int lane = idx & 31;
    int kc = (idx >> 5) & 63;
    int m16 = idx >> 11;
    int r = lane >> 2;
    int t4 = lane & 3;
    int m0 = m16 * 16;
    int k0 = kc * 16 + 2 * t4;
    float2 f0 = *(const float2*)&x[(size_t)(m0 + r) * I + k0];
    float2 f1 = *(const float2*)&x[(size_t)(m0 + r + 8) * I + k0];
    float2 f2 = *(const float2*)&x[(size_t)(m0 + r) * I + k0 + 8];
    float2 f3 = *(const float2*)&x[(size_t)(m0 + r + 8) * I + k0 + 8];
    __half2 h0 = __float22half2_rn(f0);
    __half2 h1 = __float22half2_rn(f1);
    __half2 h2 = __float22half2_rn(f2);
    __half2 h3 = __float22half2_rn(f3);
    uint4 v;
    v.x = *(unsigned*)&h0; v.y = *(unsigned*)&h1;
    v.z = *(unsigned*)&h2; v.w = *(unsigned*)&h3;
    g_xa[idx] = v;
}

// ---------------------------------------------------------------------------
// Prepack Wih (both dirs) -> b-fragments. idx -> [n16][kc][lane]
// uint4 = { b0(n8 lo), b1(n8 lo), b0(n8 hi), b1(n8 hi) }
// ---------------------------------------------------------------------------
__global__ void prepack_w(const float* __restrict__ Wf,
                          const float* __restrict__ Wb) {
    int idx = blockIdx.x * blockDim.x + threadIdx.x;
    if (idx >= N16 * KC * 32) return;
    int lane = idx & 31;
    int kc = (idx >> 5) & 63;
    int n16 = idx >> 11;
    int n = n16 * 16;
    const float* W = (n >= G4) ? Wb : Wf;
    int g = n & (G4 - 1);
    int r = lane >> 2;
    int t4 = lane & 3;
    int k0 = kc * 16 + 2 * t4;
    float2 f0 = *(const float2*)&W[(size_t)(g + r) * H + k0];       // b0 lo
    float2 f1 = *(const float2*)&W[(size_t)(g + r) * H + k0 + 8];   // b1 lo
    float2 f2 = *(const float2*)&W[(size_t)(g + r + 8) * H + k0];   // b0 hi
    float2 f3 = *(const float2*)&W[(size_t)(g + r + 8) * H + k0 + 8];
    __half2 h0 = __float22half2_rn(f0);
    __half2 h1 = __float22half2_rn(f1);
    __half2 h2 = __float22half2_rn(f2);
    __half2 h3 = __float22half2_rn(f3);
    uint4 v;
    v.x = *(unsigned*)&h0; v.y = *(unsigned*)&h1;
    v.z = *(unsigned*)&h2; v.w = *(unsigned*)&h3;
    g_wb[idx] = v;
}

// ---------------------------------------------------------------------------
// xg GEMM: C[m][n] = x @ Wih^T (+bias in epilogue), fp16 HMMA.
// CTA tile 256x128, 8 warps m64n64, BK=32 (2 k16), cp.async double buffer.
// grid = (N_ALL/128, M_ALL/256) = (64, 64)
// ---------------------------------------------------------------------------
__global__ __launch_bounds__(256)
void xg_gemm_hmma(const float* __restrict__ bihf, const float* __restrict__ bhhf,
                  const float* __restrict__ bihb, const float* __restrict__ bhhb) {
    __shared__ uint4 sA[2][1024];   // [stage][(m16l*2 + kcl)*32 + lane]
    __shared__ uint4 sB[2][512];    // [stage][(n16l*2 + kcl)*32 + lane]

    const int tid = threadIdx.x;
    const int m0 = blockIdx.y * 256;
    const int n0 = blockIdx.x * 128;
    const int m16g0 = m0 >> 4;
    const int n16g0 = n0 >> 4;

    const int warp = tid >> 5;
    const int lane = tid & 31;
    const int wm = warp >> 1;       // 0..3
    const int wn = warp & 1;        // 0..1
    const int gID = lane >> 2;
    const int t4 = lane & 3;

    float acc[4][8][4];
#pragma unroll
    for (int i = 0; i < 4; i++)
#pragma unroll
        for (int j = 0; j < 8; j++)
#pragma unroll
            for (int q = 0; q < 4; q++) acc[i][j][q] = 0.f;

    // per-thread copy indices
    int a_m16l[4], a_kcl[4], a_lane[4];
#pragma unroll
    for (int j = 0; j < 4; j++) {
        int i = tid + j * 256;
        a_m16l[j] = i >> 6;
        a_kcl[j] = (i >> 5) & 1;
        a_lane[j] = i & 31;
    }
    int b_n16l[2], b_kcl[2], b_lane[2];
#pragma unroll
    for (int j = 0; j < 2; j++) {
        int i = tid + j * 256;
        b_n16l[j] = i >> 6;
        b_kcl[j] = (i >> 5) & 1;
        b_lane[j] = i & 31;
    }

    auto issue_stage = [&](int buf, int ks) {
#pragma unroll
        for (int j = 0; j < 4; j++) {
            const uint4* src = g_xa +
                ((size_t)(m16g0 + a_m16l[j]) * KC + ks * 2 + a_kcl[j]) * 32 + a_lane[j];
            unsigned dst = (unsigned)__cvta_generic_to_shared(
                &sA[buf][(a_m16l[j] * 2 + a_kcl[j]) * 32 + a_lane[j]]);
            CP_ASYNC16(dst, src);
        }
#pragma unroll
        for (int j = 0; j < 2; j++) {
            const uint4* src = g_wb +
                ((size_t)(n16g0 + b_n16l[j]) * KC + ks * 2 + b_kcl[j]) * 32 + b_lane[j];
            unsigned dst = (unsigned)__cvta_generic_to_shared(
                &sB[buf][(b_n16l[j] * 2 + b_kcl[j]) * 32 + b_lane[j]]);
            CP_ASYNC16(dst, src);
        }
        CP_COMMIT();
    };

    issue_stage(0, 0);

    for (int ks = 0; ks < 32; ks++) {
        const int cur = ks & 1;
        if (ks + 1 < 32) {
            issue_stage(cur ^ 1, ks + 1);
            CP_WAIT1();
        } else {
            CP_WAIT0();
        }
        __syncthreads();

#pragma unroll
        for (int kcl = 0; kcl < 2; kcl++) {
            uint4 a[4], b[4];
#pragma unroll
            for (int i = 0; i < 4; i++)
                a[i] = sA[cur][((wm * 4 + i) * 2 + kcl) * 32 + lane];
#pragma unroll
            for (int j = 0; j < 4; j++)
                b[j] = sB[cur][((wn * 4 + j) * 2 + kcl) * 32 + lane];
#pragma unroll
            for (int i = 0; i < 4; i++)
#pragma unroll
                for (int j = 0; j < 4; j++) {
                    mma_fp16(acc[i][2 * j],     a[i], b[j].x, b[j].y);
                    mma_fp16(acc[i][2 * j + 1], a[i], b[j].z, b[j].w);
                }
        }
        __syncthreads();
    }

    // epilogue: add bias, store fp16 to g_xg [dir][m][4096]
    const int d = n0 >> 12;
    const float* bih = d ? bihb : bihf;
    const float* bhh = d ? bhhb : bhhf;
    __half* outd = g_xg + (size_t)d * M_ALL * G4;

#pragma unroll
    for (int j8 = 0; j8 < 8; j8++) {
        int col = n0 + wn * 64 + j8 * 8 + 2 * t4;
        int g = col & (G4 - 1);
        float bx = bih[g] + bhh[g];
        float by = bih[g + 1] + bhh[g + 1];
#pragma unroll
        for (int i = 0; i < 4; i++) {
            int row0 = m0 + wm * 64 + i * 16 + gID;
            __half2 v0 = __floats2half2_rn(acc[i][j8][0] + bx, acc[i][j8][1] + by);
            __half2 v1 = __floats2half2_rn(acc[i][j8][2] + bx, acc[i][j8][3] + by);
            *(__half2*)&outd[(size_t)row0 * G4 + g] = v0;
            *(__half2*)&outd[(size_t)(row0 + 8) * G4 + g] = v1;
        }
    }
}

// ---------------------------------------------------------------------------
// Persistent recurrence kernel (as R3, + xg prefetch + fast activations)
// ---------------------------------------------------------------------------
__global__ __launch_bounds__(THREADS, 1)
void lstm_persistent(const float* __restrict__ Whhf,
                     const float* __restrict__ Whhb,
                     const float* __restrict__ c0f,
                     const float* __restrict__ c0b,
                     float* __restrict__ out) {
    extern __shared__ char smem[];
    uint4*  Wf = (uint4*)smem;
    __half* Hs = (__half*)(smem + SMEM_W);
    float*  Gs = (float*)(smem + SMEM_W + SMEM_HS);

    const int tid = threadIdx.x;
    const int d = blockIdx.x >> 6;
    const int s = blockIdx.x & 63;
    const int j0 = s * 16;
    const float* Whh = d ? Whhb : Whhf;

    for (int s0 = tid; s0 < 4 * 64 * 32; s0 += THREADS) {
        int l  = s0 & 31;
        int kc = (s0 >> 5) & 63;
        int mw = s0 >> 11;
        int r  = l >> 2;
        int t4 = l & 3;
        int row0 = mw * H + j0 + r;
        int row1 = row0 + 8;
        int k0 = kc * 16 + 2 * t4;
        float2 f0 = *(const float2*)&Whh[(size_t)row0 * H + k0];
        float2 f1 = *(const float2*)&Whh[(size_t)row1 * H + k0];
        float2 f2 = *(const float2*)&Whh[(size_t)row0 * H + k0 + 8];
        float2 f3 = *(const float2*)&Whh[(size_t)row1 * H + k0 + 8];
        __half2 h0 = __float22half2_rn(f0);
        __half2 h1 = __float22half2_rn(f1);
        __half2 h2 = __float22half2_rn(f2);
        __half2 h3 = __float22half2_rn(f3);
        uint4 v;
        v.x = *(unsigned*)&h0; v.y = *(unsigned*)&h1;
        v.z = *(unsigned*)&h2; v.w = *(unsigned*)&h3;
        Wf[s0] = v;
    }

    float c_reg[2];
#pragma unroll
    for (int rep = 0; rep < 2; rep++) {
        int id = tid + rep * 256;
        int jj = id & 15;
        int b = id >> 4;
        c_reg[rep] = (d ? c0b : c0f)[b * H + j0 + jj];
    }

    const int warp = tid >> 5;
    const int lane = tid & 31;
    const int mw = warp & 3;
    const int nw = warp >> 2;
    const int gID = lane >> 2;
    const int t4 = lane & 3;
    const uint4* wfrag = Wf + mw * 2048 + lane;
    const __half* hp0 = &Hs[(nw * 16 + gID) * HS_PITCH + 2 * t4];
    const __half* hp1 = hp0 + 8 * HS_PITCH;

    const size_t xg_dir = (size_t)d * M_ALL * G4;
    volatile unsigned* barp = &g_bar[d];

    for (int t = 0; t < T; t++) {
        const int p = t & 1;
        const int t_eff = d ? (T - 1 - t) : t;

        // ---- prefetch xg into registers (hides DRAM latency) ----
        float xi[2][4];
#pragma unroll
        for (int rep = 0; rep < 2; rep++) {
            int id = tid + rep * 256;
            int jj = id & 15;
            int b = id >> 4;
            const __half* xgp = g_xg + xg_dir
                              + (size_t)(t_eff * B + b) * G4 + j0 + jj;
            xi[rep][0] = __half2float(__ldcg(xgp));
            xi[rep][1] = __half2float(__ldcg(xgp + H));
            xi[rep][2] = __half2float(__ldcg(xgp + 2 * H));
            xi[rep][3] = __half2float(__ldcg(xgp + 3 * H));
        }

        // ---- stage h (fp16) into Hs ----
        const uint4* src = (const uint4*)&g_hstage[p][d][0][0];
#pragma unroll
        for (int i = 0; i < 16; i++) {
            int s1 = tid + i * 256;
            int b = s1 >> 7;
            int q = s1 & 127;
            uint4 v = __ldcg(src + s1);
            *(uint4*)&Hs[b * HS_PITCH + q * 8] = v;
        }
        __syncthreads();

        float acc0[4] = {0.f, 0.f, 0.f, 0.f};
        float acc1[4] = {0.f, 0.f, 0.f, 0.f};
#pragma unroll 8
        for (int kc = 0; kc < 64; kc++) {
            uint4 a = wfrag[kc * 32];
            unsigned b00 = *(const unsigned*)(hp0 + kc * 16);
            unsigned b01 = *(const unsigned*)(hp0 + kc * 16 + 8);
            unsigned b10 = *(const unsigned*)(hp1 + kc * 16);
            unsigned b11 = *(const unsigned*)(hp1 + kc * 16 + 8);
            mma_fp16(acc0, a, b00, b01);
            mma_fp16(acc1, a, b10, b11);
        }

        {
            int row = mw * 16 + gID;
            int cb = nw * 16 + 2 * t4;
            Gs[row * 33 + cb]           = acc0[0];
            Gs[row * 33 + cb + 1]       = acc0[1];
            Gs[(row + 8) * 33 + cb]     = acc0[2];
            Gs[(row + 8) * 33 + cb + 1] = acc0[3];
            Gs[row * 33 + cb + 8]       = acc1[0];
            Gs[row * 33 + cb + 9]       = acc1[1];
            Gs[(row + 8) * 33 + cb + 8] = acc1[2];
            Gs[(row + 8) * 33 + cb + 9] = acc1[3];
        }
        __syncthreads();

#pragma unroll
        for (int rep = 0; rep < 2; rep++) {
            int id = tid + rep * 256;
            int jj = id & 15;
            int b = id >> 4;
            float ig = Gs[(0  + jj) * 33 + b] + xi[rep][0];
            float fg = Gs[(16 + jj) * 33 + b] + xi[rep][1];
            float gg = Gs[(32 + jj) * 33 + b] + xi[rep][2];
            float og = Gs[(48 + jj) * 33 + b] + xi[rep][3];
            ig = sig_(ig);
            fg = sig_(fg);
            og = sig_(og);
            gg = tanh_(gg);
            float cn = fg * c_reg[rep] + ig * gg;
            c_reg[rep] = cn;
            float hn = og * tanh_(cn);
            out[(size_t)t_eff * B * OUT_COLS + (size_t)b * OUT_COLS
                + (size_t)d * H + j0 + jj] = hn;
            g_hstage[p ^ 1][d][b][j0 + jj] = __float2half(hn);
        }

        if (t + 1 < T) {
            __syncthreads();
            if (tid == 0) {
                __threadfence();
                atomicAdd(&g_bar[d], 1u);
                unsigned tgt = (unsigned)CTAS_PER_DIR * (t + 1);
                while (*barp < tgt) { }
                __threadfence();
            }
            __syncthreads();
        }
    }

#pragma unroll
    for (int rep = 0; rep < 2; rep++) {
        int id = tid + rep * 256;
        int jj = id & 15;
        int b = id >> 4;
        g_c[(size_t)d * B * H + (size_t)b * H + j0 + jj] = c_reg[rep];
    }
}

// ---------------------------------------------------------------------------
__global__ void finalize_kernel(float* __restrict__ out) {
    int i = blockIdx.x * blockDim.x + threadIdx.x;
    if (i >= B * H) return;
    int b = i >> 10;
    int j = i & (H - 1);
    float* tail = out + OUT_MAIN;
    tail[i]             = out[(size_t)(T - 1) * B * OUT_COLS + (size_t)b * OUT_COLS + j];
    tail[B * H + i]     = g_c[i];
    tail[2 * B * H + i] = out[(size_t)b * OUT_COLS + H + j];
    tail[3 * B * H + i] = g_c[B * H + i];
}

// ---------------------------------------------------------------------------
extern "C" void kernel_launch(void* const* d_in, const int* in_sizes, int n_in,
                              void* d_out, int out_size) {
    const float* x    = (const float*)d_in[0];
    const float* h0f  = (const float*)d_in[1];
    const float* c0f  = (const float*)d_in[2];
    const float* h0b  = (const float*)d_in[3];
    const float* c0b  = (const float*)d_in[4];
    const float* Wihf = (const float*)d_in[5];
    const float* Whhf = (const float*)d_in[6];
    const float* bihf = (const float*)d_in[7];
    const float* bhhf = (const float*)d_in[8];
    const float* Wihb = (const float*)d_in[9];
    const float* Whhb = (const float*)d_in[10];
    const float* bihb = (const float*)d_in[11];
    const float* bhhb = (const float*)d_in[12];
    float* out = (float*)d_out;

    static int smem_set = 0;
    if (!smem_set) {
        cudaFuncSetAttribute(lstm_persistent,
                             cudaFuncAttributeMaxDynamicSharedMemorySize,
                             SMEM_BYTES);
        smem_set = 1;
    }

    init_kernel<<<(B * H + 255) / 256, 256>>>(h0f, h0b);
    prepack_x<<<(M16 * KC * 32 + 255) / 256, 256>>>(x);
    prepack_w<<<(N16 * KC * 32 + 255) / 256, 256>>>(Wihf, Wihb);

    dim3 grid_xg(N_ALL / 128, M_ALL / 256);   // (64, 64)
    xg_gemm_hmma<<<grid_xg, 256>>>(bihf, bhhf, bihb, bhhb);

    lstm_persistent<<<CTAS, THREADS, SMEM_BYTES>>>(Whhf, Whhb, c0f, c0b, out);

    finalize_kernel<<<(B * H + 255) / 256, 256>>>(out);
}

// round 5
// speedup vs baseline: 8.1366x; 1.1300x over previous
#include <cuda_runtime.h>
#include <cuda_fp16.h>
#include <math.h>

// ---------------------------------------------------------------------------
// Bidirectional LSTM: T=512, B=32, I=1024, H=1024.
// Round 5:
//   - persistent recurrence: W fragments cached in registers (40/64 chunks),
//     cp.async split-k staging of h (latency overlapped with mma),
//     xg prefetch + out store hidden behind the grid-barrier spin.
//   - xg GEMM: 3-stage cp.async pipeline, one syncthreads per k-step.
// ---------------------------------------------------------------------------

namespace {
constexpr int T = 512;
constexpr int B = 32;
constexpr int I = 1024;
constexpr int H = 1024;
constexpr int G4 = 4 * H;          // 4096
constexpr int N_ALL = 2 * G4;      // 8192
constexpr int OUT_COLS = 2 * H;    // 2048
constexpr int M_ALL = T * B;       // 16384
constexpr long long OUT_MAIN = (long long)T * B * OUT_COLS;

constexpr int CTAS = 128;
constexpr int THREADS = 256;
constexpr int CTAS_PER_DIR = 64;

constexpr int HS_PITCH = 1032;     // halves
constexpr int SMEM_W  = 4 * 64 * 32 * 16;           // 131072
constexpr int SMEM_HS = 32 * HS_PITCH * 2;          // 66048
constexpr int SMEM_GS = 4 * 16 * 33 * 4;            // 8448
constexpr int SMEM_BYTES = SMEM_W + SMEM_HS + SMEM_GS;

constexpr int KC = 64;
constexpr int M16 = M_ALL / 16;    // 1024
constexpr int N16 = N_ALL / 16;    // 512

constexpr int NREG = 40;           // W k-chunks cached in registers

constexpr int GEMM_SMEM = 3 * (1024 + 512) * 16;    // 73728 (3-stage)
}

__device__ __half g_xg[2LL * M_ALL * G4];
__device__ float g_c[2 * B * H];
__device__ __half g_hstage[2][2][B][H];
__device__ unsigned g_bar[2];
__device__ uint4 g_xa[(long long)M16 * KC * 32];
__device__ uint4 g_wb[(long long)N16 * KC * 32];

__device__ __forceinline__ void mma_fp16(float* d, const uint4& a,
                                         unsigned b0, unsigned b1) {
    asm volatile(
        "mma.sync.aligned.m16n8k16.row.col.f32.f16.f16.f32 "
        "{%0,%1,%2,%3}, {%4,%5,%6,%7}, {%8,%9}, {%0,%1,%2,%3};"
        : "+f"(d[0]), "+f"(d[1]), "+f"(d[2]), "+f"(d[3])
        : "r"(a.x), "r"(a.y), "r"(a.z), "r"(a.w), "r"(b0), "r"(b1));
}

__device__ __forceinline__ float sig_(float x) {
    return 1.f / (1.f + __expf(-x));
}
__device__ __forceinline__ float tanh_(float x) {
    float t = __expf(-2.f * fabsf(x));
    float r = (1.f - t) / (1.f + t);
    return x < 0.f ? -r : r;
}

#define CP_ASYNC16(smem_u32, gptr) \
    asm volatile("cp.async.cg.shared.global [%0], [%1], 16;" \
                 :: "r"(smem_u32), "l"(gptr))
#define CP_COMMIT() asm volatile("cp.async.commit_group;")
#define CP_WAIT1() asm volatile("cp.async.wait_group 1;")
#define CP_WAIT0() asm volatile("cp.async.wait_group 0;")

// ---------------------------------------------------------------------------
__global__ void init_kernel(const float* __restrict__ h0f,
                            const float* __restrict__ h0b) {
    int i = blockIdx.x * blockDim.x + threadIdx.x;
    if (i == 0) { g_bar[0] = 0; g_bar[1] = 0; }
    if (i < B * H) {
        int b = i >> 10;
        int k = i & 1023;
        g_hstage[0][0][b][k] = __float2half(h0f[i]);
        g_hstage[0][1][b][k] = __float2half(h0b[i]);
    }
}

// ---------------------------------------------------------------------------
__global__ void prepack_x(const float* __restrict__ x) {
    int idx = blockIdx.x * blockDim.x + threadIdx.x;
    if (idx >= M16 * KC * 32) return;
    int lane = idx & 31;
    int kc = (idx >> 5) & 63;
    int m16 = idx >> 11;
    int r = lane >> 2;
    int t4 = lane & 3;
    int m0 = m16 * 16;
    int k0 = kc * 16 + 2 * t4;
    float2 f0 = *(const float2*)&x[(size_t)(m0 + r) * I + k0];
    float2 f1 = *(const float2*)&x[(size_t)(m0 + r + 8) * I + k0];
    float2 f2 = *(const float2*)&x[(size_t)(m0 + r) * I + k0 + 8];
    float2 f3 = *(const float2*)&x[(size_t)(m0 + r + 8) * I + k0 + 8];
    __half2 h0 = __float22half2_rn(f0);
    __half2 h1 = __float22half2_rn(f1);
    __half2 h2 = __float22half2_rn(f2);
    __half2 h3 = __float22half2_rn(f3);
    uint4 v;
    v.x = *(unsigned*)&h0; v.y = *(unsigned*)&h1;
    v.z = *(unsigned*)&h2; v.w = *(unsigned*)&h3;
    g_xa[idx] = v;
}

__global__ void prepack_w(const float* __restrict__ Wf,
                          const float* __restrict__ Wb) {
    int idx = blockIdx.x * blockDim.x + threadIdx.x;
    if (idx >= N16 * KC * 32) return;
    int lane = idx & 31;
    int kc = (idx >> 5) & 63;
    int n16 = idx >> 11;
    int n = n16 * 16;
    const float* W = (n >= G4) ? Wb : Wf;
    int g = n & (G4 - 1);
    int r = lane >> 2;
    int t4 = lane & 3;
    int k0 = kc * 16 + 2 * t4;
    float2 f0 = *(const float2*)&W[(size_t)(g + r) * H + k0];
    float2 f1 = *(const float2*)&W[(size_t)(g + r) * H + k0 + 8];
    float2 f2 = *(const float2*)&W[(size_t)(g + r + 8) * H + k0];
    float2 f3 = *(const float2*)&W[(size_t)(g + r + 8) * H + k0 + 8];
    __half2 h0 = __float22half2_rn(f0);
    __half2 h1 = __float22half2_rn(f1);
    __half2 h2 = __float22half2_rn(f2);
    __half2 h3 = __float22half2_rn(f3);
    uint4 v;
    v.x = *(unsigned*)&h0; v.y = *(unsigned*)&h1;
    v.z = *(unsigned*)&h2; v.w = *(unsigned*)&h3;
    g_wb[idx] = v;
}

// ---------------------------------------------------------------------------
// xg GEMM, 3-stage cp.async pipeline. CTA tile 256x128, 8 warps m64n64.
// ---------------------------------------------------------------------------
__global__ __launch_bounds__(256)
void xg_gemm_hmma(const float* __restrict__ bihf, const float* __restrict__ bhhf,
                  const float* __restrict__ bihb, const float* __restrict__ bhhb) {
    extern __shared__ char gsm[];
    uint4* sA = (uint4*)gsm;                    // 3 x 1024
    uint4* sB = (uint4*)(gsm + 3 * 16384);      // 3 x 512

    const int tid = threadIdx.x;
    const int m0 = blockIdx.y * 256;
    const int n0 = blockIdx.x * 128;
    const int m16g0 = m0 >> 4;
    const int n16g0 = n0 >> 4;

    const int warp = tid >> 5;
    const int lane = tid & 31;
    const int wm = warp >> 1;
    const int wn = warp & 1;
    const int gID = lane >> 2;
    const int t4 = lane & 3;

    float acc[4][8][4];
#pragma unroll
    for (int i = 0; i < 4; i++)
#pragma unroll
        for (int j = 0; j < 8; j++)
#pragma unroll
            for (int q = 0; q < 4; q++) acc[i][j][q] = 0.f;

    int a_m16l[4], a_kcl[4], a_lane[4];
#pragma unroll
    for (int j = 0; j < 4; j++) {
        int i = tid + j * 256;
        a_m16l[j] = i >> 6;
        a_kcl[j] = (i >> 5) & 1;
        a_lane[j] = i & 31;
    }
    int b_n16l[2], b_kcl[2], b_lane[2];
#pragma unroll
    for (int j = 0; j < 2; j++) {
        int i = tid + j * 256;
        b_n16l[j] = i >> 6;
        b_kcl[j] = (i >> 5) & 1;
        b_lane[j] = i & 31;
    }

    auto issue_stage = [&](int buf, int ks) {
#pragma unroll
        for (int j = 0; j < 4; j++) {
            const uint4* src = g_xa +
                ((size_t)(m16g0 + a_m16l[j]) * KC + ks * 2 + a_kcl[j]) * 32 + a_lane[j];
            unsigned dst = (unsigned)__cvta_generic_to_shared(
                &sA[buf * 1024 + (a_m16l[j] * 2 + a_kcl[j]) * 32 + a_lane[j]]);
            CP_ASYNC16(dst, src);
        }
#pragma unroll
        for (int j = 0; j < 2; j++) {
            const uint4* src = g_wb +
                ((size_t)(n16g0 + b_n16l[j]) * KC + ks * 2 + b_kcl[j]) * 32 + b_lane[j];
            unsigned dst = (unsigned)__cvta_generic_to_shared(
                &sB[buf * 512 + (b_n16l[j] * 2 + b_kcl[j]) * 32 + b_lane[j]]);
            CP_ASYNC16(dst, src);
        }
        CP_COMMIT();
    };

    issue_stage(0, 0);
    issue_stage(1, 1);

    int cur = 0;
    for (int ks = 0; ks < 32; ks++) {
        if (ks < 31) { CP_WAIT1(); } else { CP_WAIT0(); }
        __syncthreads();
        if (ks + 2 < 32) {
            int nbuf = cur + 2;
            if (nbuf >= 3) nbuf -= 3;
            issue_stage(nbuf, ks + 2);
        }

#pragma unroll
        for (int kcl = 0; kcl < 2; kcl++) {
            uint4 a[4], b[4];
#pragma unroll
            for (int i = 0; i < 4; i++)
                a[i] = sA[cur * 1024 + ((wm * 4 + i) * 2 + kcl) * 32 + lane];
#pragma unroll
            for (int j = 0; j < 4; j++)
                b[j] = sB[cur * 512 + ((wn * 4 + j) * 2 + kcl) * 32 + lane];
#pragma unroll
            for (int i = 0; i < 4; i++)
#pragma unroll
                for (int j = 0; j < 4; j++) {
                    mma_fp16(acc[i][2 * j],     a[i], b[j].x, b[j].y);
                    mma_fp16(acc[i][2 * j + 1], a[i], b[j].z, b[j].w);
                }
        }
        cur++;
        if (cur == 3) cur = 0;
    }

    const int d = n0 >> 12;
    const float* bih = d ? bihb : bihf;
    const float* bhh = d ? bhhb : bhhf;
    __half* outd = g_xg + (size_t)d * M_ALL * G4;

#pragma unroll
    for (int j8 = 0; j8 < 8; j8++) {
        int col = n0 + wn * 64 + j8 * 8 + 2 * t4;
        int g = col & (G4 - 1);
        float bx = bih[g] + bhh[g];
        float by = bih[g + 1] + bhh[g + 1];
#pragma unroll
        for (int i = 0; i < 4; i++) {
            int row0 = m0 + wm * 64 + i * 16 + gID;
            __half2 v0 = __floats2half2_rn(acc[i][j8][0] + bx, acc[i][j8][1] + by);
            __half2 v1 = __floats2half2_rn(acc[i][j8][2] + bx, acc[i][j8][3] + by);
            *(__half2*)&outd[(size_t)row0 * G4 + g] = v0;
            *(__half2*)&outd[(size_t)(row0 + 8) * G4 + g] = v1;
        }
    }
}

// ---------------------------------------------------------------------------
// Persistent recurrence kernel.
// ---------------------------------------------------------------------------
#define MMA_STEP(AFRAG, KCI) do {                                   \
    unsigned b00 = *(const unsigned*)(hp0 + (KCI) * 16);            \
    unsigned b01 = *(const unsigned*)(hp0 + (KCI) * 16 + 8);        \
    unsigned b10 = *(const unsigned*)(hp1 + (KCI) * 16);            \
    unsigned b11 = *(const unsigned*)(hp1 + (KCI) * 16 + 8);        \
    mma_fp16(acc0, (AFRAG), b00, b01);                              \
    mma_fp16(acc1, (AFRAG), b10, b11);                              \
} while (0)

__global__ __launch_bounds__(THREADS, 1)
void lstm_persistent(const float* __restrict__ Whhf,
                     const float* __restrict__ Whhb,
                     const float* __restrict__ c0f,
                     const float* __restrict__ c0b,
                     float* __restrict__ out) {
    extern __shared__ char smem[];
    uint4*  Wf = (uint4*)smem;
    __half* Hs = (__half*)(smem + SMEM_W);
    float*  Gs = (float*)(smem + SMEM_W + SMEM_HS);

    const int tid = threadIdx.x;
    const int d = blockIdx.x >> 6;
    const int s = blockIdx.x & 63;
    const int j0 = s * 16;
    const float* Whh = d ? Whhb : Whhf;

    // ---- prepack W slice into fp16 fragment layout ----
    for (int s0 = tid; s0 < 4 * 64 * 32; s0 += THREADS) {
        int l  = s0 & 31;
        int kc = (s0 >> 5) & 63;
        int mw = s0 >> 11;
        int r  = l >> 2;
        int t4 = l & 3;
        int row0 = mw * H + j0 + r;
        int row1 = row0 + 8;
        int k0 = kc * 16 + 2 * t4;
        float2 f0 = *(const float2*)&Whh[(size_t)row0 * H + k0];
        float2 f1 = *(const float2*)&Whh[(size_t)row1 * H + k0];
        float2 f2 = *(const float2*)&Whh[(size_t)row0 * H + k0 + 8];
        float2 f3 = *(const float2*)&Whh[(size_t)row1 * H + k0 + 8];
        __half2 h0 = __float22half2_rn(f0);
        __half2 h1 = __float22half2_rn(f1);
        __half2 h2 = __float22half2_rn(f2);
        __half2 h3 = __float22half2_rn(f3);
        uint4 v;
        v.x = *(unsigned*)&h0; v.y = *(unsigned*)&h1;
        v.z = *(unsigned*)&h2; v.w = *(unsigned*)&h3;
        Wf[s0] = v;
    }
    __syncthreads();

    const int warp = tid >> 5;
    const int lane = tid & 31;
    const int mw = warp & 3;
    const int nw = warp >> 2;
    const int gID = lane >> 2;
    const int t4 = lane & 3;
    const uint4* wfrag = Wf + mw * 2048 + lane;
    const __half* hp0 = &Hs[(nw * 16 + gID) * HS_PITCH + 2 * t4];
    const __half* hp1 = hp0 + 8 * HS_PITCH;

    // ---- cache first NREG W k-chunks in registers ----
    uint4 wreg[NREG];
#pragma unroll
    for (int kc = 0; kc < NREG; kc++) wreg[kc] = wfrag[kc * 32];

    float c_reg[2];
#pragma unroll
    for (int rep = 0; rep < 2; rep++) {
        int id = tid + rep * 256;
        int jj = id & 15;
        int b = id >> 4;
        c_reg[rep] = (d ? c0b : c0f)[b * H + j0 + jj];
    }

    const size_t xg_dir = (size_t)d * M_ALL * G4;
    volatile unsigned* barp = &g_bar[d];

    // ---- prefetch xg for step 0 ----
    float xi[2][4];
    {
        int te0 = d ? (T - 1) : 0;
#pragma unroll
        for (int rep = 0; rep < 2; rep++) {
            int id = tid + rep * 256;
            int jj = id & 15;
            int b = id >> 4;
            const __half* xgp = g_xg + xg_dir
                              + (size_t)(te0 * B + b) * G4 + j0 + jj;
            xi[rep][0] = __half2float(__ldcg(xgp));
            xi[rep][1] = __half2float(__ldcg(xgp + H));
            xi[rep][2] = __half2float(__ldcg(xgp + 2 * H));
            xi[rep][3] = __half2float(__ldcg(xgp + 3 * H));
        }
    }

    for (int t = 0; t < T; t++) {
        const int p = t & 1;
        const int t_eff = d ? (T - 1 - t) : t;

        // ---- stage h via cp.async in two k-halves ----
        const uint4* src = (const uint4*)&g_hstage[p][d][0][0];  // [b(32)][q(128)]
#pragma unroll
        for (int hh = 0; hh < 2; hh++) {
#pragma unroll
            for (int i = 0; i < 8; i++) {
                int j = tid + i * 256;           // 0..2047
                int b = j >> 6;
                int q = (j & 63) + hh * 64;
                unsigned dst = (unsigned)__cvta_generic_to_shared(
                    &Hs[b * HS_PITCH + q * 8]);
                CP_ASYNC16(dst, src + b * 128 + q);
            }
            CP_COMMIT();
        }

        float acc0[4] = {0.f, 0.f, 0.f, 0.f};
        float acc1[4] = {0.f, 0.f, 0.f, 0.f};

        CP_WAIT1();
        __syncthreads();
#pragma unroll
        for (int kc = 0; kc < 32; kc++) MMA_STEP(wreg[kc], kc);

        CP_WAIT0();
        __syncthreads();
#pragma unroll
        for (int kc = 32; kc < NREG; kc++) MMA_STEP(wreg[kc], kc);
#pragma unroll 8
        for (int kc = NREG; kc < 64; kc++) {
            uint4 a = wfrag[kc * 32];
            MMA_STEP(a, kc);
        }

        // ---- stage gate pre-activations ----
        {
            int row = mw * 16 + gID;
            int cb = nw * 16 + 2 * t4;
            Gs[row * 33 + cb]           = acc0[0];
            Gs[row * 33 + cb + 1]       = acc0[1];
            Gs[(row + 8) * 33 + cb]     = acc0[2];
            Gs[(row + 8) * 33 + cb + 1] = acc0[3];
            Gs[row * 33 + cb + 8]       = acc1[0];
            Gs[row * 33 + cb + 9]       = acc1[1];
            Gs[(row + 8) * 33 + cb + 8] = acc1[2];
            Gs[(row + 8) * 33 + cb + 9] = acc1[3];
        }
        __syncthreads();

        // ---- pointwise cell update (h -> hstage; out deferred) ----
        float hn_keep[2];
#pragma unroll
        for (int rep = 0; rep < 2; rep++) {
            int id = tid + rep * 256;
            int jj = id & 15;
            int b = id >> 4;
            float ig = Gs[(0  + jj) * 33 + b] + xi[rep][0];
            float fg = Gs[(16 + jj) * 33 + b] + xi[rep][1];
            float gg = Gs[(32 + jj) * 33 + b] + xi[rep][2];
            float og = Gs[(48 + jj) * 33 + b] + xi[rep][3];
            ig = sig_(ig);
            fg = sig_(fg);
            og = sig_(og);
            gg = tanh_(gg);
            float cn = fg * c_reg[rep] + ig * gg;
            c_reg[rep] = cn;
            float hn = og * tanh_(cn);
            hn_keep[rep] = hn;
            g_hstage[p ^ 1][d][b][j0 + jj] = __float2half(hn);
        }

        __threadfence();
        __syncthreads();     // all hstage stores fenced & done CTA-wide

        if (t + 1 < T && tid == 0) atomicAdd(&g_bar[d], 1u);

        // ---- hidden behind the barrier spin: out store + next xg prefetch
#pragma unroll
        for (int rep = 0; rep < 2; rep++) {
            int id = tid + rep * 256;
            int jj = id & 15;
            int b = id >> 4;
            out[(size_t)t_eff * B * OUT_COLS + (size_t)b * OUT_COLS
                + (size_t)d * H + j0 + jj] = hn_keep[rep];
        }
        if (t + 1 < T) {
            int ten = d ? (T - 2 - t) : (t + 1);
#pragma unroll
            for (int rep = 0; rep < 2; rep++) {
                int id = tid + rep * 256;
                int jj = id & 15;
                int b = id >> 4;
                const __half* xgp = g_xg + xg_dir
                                  + (size_t)(ten * B + b) * G4 + j0 + jj;
                xi[rep][0] = __half2float(__ldcg(xgp));
                xi[rep][1] = __half2float(__ldcg(xgp + H));
                xi[rep][2] = __half2float(__ldcg(xgp + 2 * H));
                xi[rep][3] = __half2float(__ldcg(xgp + 3 * H));
            }
            if (tid == 0) {
                unsigned tgt = (unsigned)CTAS_PER_DIR * (t + 1);
                while (*barp < tgt) { }
            }
            __syncthreads();
        }
    }

#pragma unroll
    for (int rep = 0; rep < 2; rep++) {
        int id = tid + rep * 256;
        int jj = id & 15;
        int b = id >> 4;
        g_c[(size_t)d * B * H + (size_t)b * H + j0 + jj] = c_reg[rep];
    }
}

// ---------------------------------------------------------------------------
__global__ void finalize_kernel(float* __restrict__ out) {
    int i = blockIdx.x * blockDim.x + threadIdx.x;
    if (i >= B * H) return;
    int b = i >> 10;
    int j = i & (H - 1);
    float* tail = out + OUT_MAIN;
    tail[i]             = out[(size_t)(T - 1) * B * OUT_COLS + (size_t)b * OUT_COLS + j];
    tail[B * H + i]     = g_c[i];
    tail[2 * B * H + i] = out[(size_t)b * OUT_COLS + H + j];
    tail[3 * B * H + i] = g_c[B * H + i];
}

// ---------------------------------------------------------------------------
extern "C" void kernel_launch(void* const* d_in, const int* in_sizes, int n_in,
                              void* d_out, int out_size) {
    const float* x    = (const float*)d_in[0];
    const float* h0f  = (const float*)d_in[1];
    const float* c0f  = (const float*)d_in[2];
    const float* h0b  = (const float*)d_in[3];
    const float* c0b  = (const float*)d_in[4];
    const float* Wihf = (const float*)d_in[5];
    const float* Whhf = (const float*)d_in[6];
    const float* bihf = (const float*)d_in[7];
    const float* bhhf = (const float*)d_in[8];
    const float* Wihb = (const float*)d_in[9];
    const float* Whhb = (const float*)d_in[10];
    const float* bihb = (const float*)d_in[11];
    const float* bhhb = (const float*)d_in[12];
    float* out = (float*)d_out;

    static int smem_set = 0;
    if (!smem_set) {
        cudaFuncSetAttribute(lstm_persistent,
                             cudaFuncAttributeMaxDynamicSharedMemorySize,
                             SMEM_BYTES);
        cudaFuncSetAttribute(xg_gemm_hmma,
                             cudaFuncAttributeMaxDynamicSharedMemorySize,
                             GEMM_SMEM);
        smem_set = 1;
    }

    init_kernel<<<(B * H + 255) / 256, 256>>>(h0f, h0b);
    prepack_x<<<(M16 * KC * 32 + 255) / 256, 256>>>(x);
    prepack_w<<<(N16 * KC * 32 + 255) / 256, 256>>>(Wihf, Wihb);

    dim3 grid_xg(N_ALL / 128, M_ALL / 256);   // (64, 64)
    xg_gemm_hmma<<<grid_xg, 256, GEMM_SMEM>>>(bihf, bhhf, bihb, bhhb);

    lstm_persistent<<<CTAS, THREADS, SMEM_BYTES>>>(Whhf, Whhb, c0f, c0b, out);

    finalize_kernel<<<(B * H + 255) / 256, 256>>>(out);
}

// round 6
// speedup vs baseline: 8.4993x; 1.0446x over previous
#include <cuda_runtime.h>
#include <cuda_fp16.h>
#include <math.h>

// ---------------------------------------------------------------------------
// Bidirectional LSTM: T=512, B=32, I=1024, H=1024.
// Round 6:
//   - xg GEMM: warp tile m64n32, CTA 128x128, <=128 regs -> 2 CTAs/SM,
//     3-stage cp.async pipeline.
//   - recurrence: 4 accumulator chains (even/odd kc), release/acquire
//     grid barrier (no per-thread threadfence).
// ---------------------------------------------------------------------------

namespace {
constexpr int T = 512;
constexpr int B = 32;
constexpr int I = 1024;
constexpr int H = 1024;
constexpr int G4 = 4 * H;          // 4096
constexpr int N_ALL = 2 * G4;      // 8192
constexpr int OUT_COLS = 2 * H;    // 2048
constexpr int M_ALL = T * B;       // 16384
constexpr long long OUT_MAIN = (long long)T * B * OUT_COLS;

constexpr int CTAS = 128;
constexpr int THREADS = 256;
constexpr int CTAS_PER_DIR = 64;

constexpr int HS_PITCH = 1032;
constexpr int SMEM_W  = 4 * 64 * 32 * 16;           // 131072
constexpr int SMEM_HS = 32 * HS_PITCH * 2;          // 66048
constexpr int SMEM_GS = 4 * 16 * 33 * 4;            // 8448
constexpr int SMEM_BYTES = SMEM_W + SMEM_HS + SMEM_GS;

constexpr int KC = 64;
constexpr int M16 = M_ALL / 16;    // 1024
constexpr int N16 = N_ALL / 16;    // 512

constexpr int NREG = 40;

constexpr int GEMM_SMEM = 3 * (512 + 512) * 16;     // 49152 (3-stage, 128x128)
}

__device__ __half g_xg[2LL * M_ALL * G4];
__device__ float g_c[2 * B * H];
__device__ __half g_hstage[2][2][B][H];
__device__ unsigned g_bar[2];
__device__ uint4 g_xa[(long long)M16 * KC * 32];
__device__ uint4 g_wb[(long long)N16 * KC * 32];

__device__ __forceinline__ void mma_fp16(float* d, const uint4& a,
                                         unsigned b0, unsigned b1) {
    asm volatile(
        "mma.sync.aligned.m16n8k16.row.col.f32.f16.f16.f32 "
        "{%0,%1,%2,%3}, {%4,%5,%6,%7}, {%8,%9}, {%0,%1,%2,%3};"
        : "+f"(d[0]), "+f"(d[1]), "+f"(d[2]), "+f"(d[3])
        : "r"(a.x), "r"(a.y), "r"(a.z), "r"(a.w), "r"(b0), "r"(b1));
}

__device__ __forceinline__ float sig_(float x) {
    return 1.f / (1.f + __expf(-x));
}
__device__ __forceinline__ float tanh_(float x) {
    float t = __expf(-2.f * fabsf(x));
    float r = (1.f - t) / (1.f + t);
    return x < 0.f ? -r : r;
}

__device__ __forceinline__ void red_release_add(unsigned* p) {
    asm volatile("red.release.gpu.global.add.u32 [%0], %1;"
                 :: "l"(p), "r"(1u) : "memory");
}
__device__ __forceinline__ unsigned ld_acquire(const unsigned* p) {
    unsigned v;
    asm volatile("ld.acquire.gpu.global.u32 %0, [%1];"
                 : "=r"(v) : "l"(p) : "memory");
    return v;
}

#define CP_ASYNC16(smem_u32, gptr) \
    asm volatile("cp.async.cg.shared.global [%0], [%1], 16;" \
                 :: "r"(smem_u32), "l"(gptr))
#define CP_COMMIT() asm volatile("cp.async.commit_group;")
#define CP_WAIT1() asm volatile("cp.async.wait_group 1;")
#define CP_WAIT0() asm volatile("cp.async.wait_group 0;")

// ---------------------------------------------------------------------------
__global__ void init_kernel(const float* __restrict__ h0f,
                            const float* __restrict__ h0b) {
    int i = blockIdx.x * blockDim.x + threadIdx.x;
    if (i == 0) { g_bar[0] = 0; g_bar[1] = 0; }
    if (i < B * H) {
        int b = i >> 10;
        int k = i & 1023;
        g_hstage[0][0][b][k] = __float2half(h0f[i]);
        g_hstage[0][1][b][k] = __float2half(h0b[i]);
    }
}

// ---------------------------------------------------------------------------
__global__ void prepack_x(const float* __restrict__ x) {
    int idx = blockIdx.x * blockDim.x + threadIdx.x;
    if (idx >= M16 * KC * 32) return;
    int lane = idx & 31;
    int kc = (idx >> 5) & 63;
    int m16 = idx >> 11;
    int r = lane >> 2;
    int t4 = lane & 3;
    int m0 = m16 * 16;
    int k0 = kc * 16 + 2 * t4;
    float2 f0 = *(const float2*)&x[(size_t)(m0 + r) * I + k0];
    float2 f1 = *(const float2*)&x[(size_t)(m0 + r + 8) * I + k0];
    float2 f2 = *(const float2*)&x[(size_t)(m0 + r) * I + k0 + 8];
    float2 f3 = *(const float2*)&x[(size_t)(m0 + r + 8) * I + k0 + 8];
    __half2 h0 = __float22half2_rn(f0);
    __half2 h1 = __float22half2_rn(f1);
    __half2 h2 = __float22half2_rn(f2);
    __half2 h3 = __float22half2_rn(f3);
    uint4 v;
    v.x = *(unsigned*)&h0; v.y = *(unsigned*)&h1;
    v.z = *(unsigned*)&h2; v.w = *(unsigned*)&h3;
    g_xa[idx] = v;
}

__global__ void prepack_w(const float* __restrict__ Wf,
                          const float* __restrict__ Wb) {
    int idx = blockIdx.x * blockDim.x + threadIdx.x;
    if (idx >= N16 * KC * 32) return;
    int lane = idx & 31;
    int kc = (idx >> 5) & 63;
    int n16 = idx >> 11;
    int n = n16 * 16;
    const float* W = (n >= G4) ? Wb : Wf;
    int g = n & (G4 - 1);
    int r = lane >> 2;
    int t4 = lane & 3;
    int k0 = kc * 16 + 2 * t4;
    float2 f0 = *(const float2*)&W[(size_t)(g + r) * H + k0];
    float2 f1 = *(const float2*)&W[(size_t)(g + r) * H + k0 + 8];
    float2 f2 = *(const float2*)&W[(size_t)(g + r + 8) * H + k0];
    float2 f3 = *(const float2*)&W[(size_t)(g + r + 8) * H + k0 + 8];
    __half2 h0 = __float22half2_rn(f0);
    __half2 h1 = __float22half2_rn(f1);
    __half2 h2 = __float22half2_rn(f2);
    __half2 h3 = __float22half2_rn(f3);
    uint4 v;
    v.x = *(unsigned*)&h0; v.y = *(unsigned*)&h1;
    v.z = *(unsigned*)&h2; v.w = *(unsigned*)&h3;
    g_wb[idx] = v;
}

// ---------------------------------------------------------------------------
// xg GEMM: CTA tile 128x128, 8 warps m64n32 (wm in {0,1}, wn in {0..3}),
// 3-stage cp.async, 2 CTAs/SM. grid = (N_ALL/128, M_ALL/128) = (64, 128).
// ---------------------------------------------------------------------------
__global__ __launch_bounds__(256, 2)
void xg_gemm_hmma(const float* __restrict__ bihf, const float* __restrict__ bhhf,
                  const float* __restrict__ bihb, const float* __restrict__ bhhb) {
    extern __shared__ char gsm[];
    uint4* sA = (uint4*)gsm;                    // 3 x 512
    uint4* sB = (uint4*)(gsm + 3 * 8192);       // 3 x 512

    const int tid = threadIdx.x;
    const int m0 = blockIdx.y * 128;
    const int n0 = blockIdx.x * 128;
    const int m16g0 = m0 >> 4;
    const int n16g0 = n0 >> 4;

    const int warp = tid >> 5;
    const int lane = tid & 31;
    const int wm = warp >> 2;       // 0..1
    const int wn = warp & 3;        // 0..3
    const int gID = lane >> 2;
    const int t4 = lane & 3;

    float acc[4][4][4];
#pragma unroll
    for (int i = 0; i < 4; i++)
#pragma unroll
        for (int j = 0; j < 4; j++)
#pragma unroll
            for (int q = 0; q < 4; q++) acc[i][j][q] = 0.f;

    // copy indices: 2 uint4 each for A and B per thread per stage
    int c_16l[2], c_kcl[2], c_lane[2];
#pragma unroll
    for (int j = 0; j < 2; j++) {
        int i = tid + j * 256;
        c_16l[j] = i >> 6;
        c_kcl[j] = (i >> 5) & 1;
        c_lane[j] = i & 31;
    }

    auto issue_stage = [&](int buf, int ks) {
#pragma unroll
        for (int j = 0; j < 2; j++) {
            const uint4* src = g_xa +
                ((size_t)(m16g0 + c_16l[j]) * KC + ks * 2 + c_kcl[j]) * 32 + c_lane[j];
            unsigned dst = (unsigned)__cvta_generic_to_shared(
                &sA[buf * 512 + (c_16l[j] * 2 + c_kcl[j]) * 32 + c_lane[j]]);
            CP_ASYNC16(dst, src);
        }
#pragma unroll
        for (int j = 0; j < 2; j++) {
            const uint4* src = g_wb +
                ((size_t)(n16g0 + c_16l[j]) * KC + ks * 2 + c_kcl[j]) * 32 + c_lane[j];
            unsigned dst = (unsigned)__cvta_generic_to_shared(
                &sB[buf * 512 + (c_16l[j] * 2 + c_kcl[j]) * 32 + c_lane[j]]);
            CP_ASYNC16(dst, src);
        }
        CP_COMMIT();
    };

    issue_stage(0, 0);
    issue_stage(1, 1);

    int cur = 0;
    for (int ks = 0; ks < 32; ks++) {
        if (ks < 31) { CP_WAIT1(); } else { CP_WAIT0(); }
        __syncthreads();
        if (ks + 2 < 32) {
            int nbuf = cur + 2;
            if (nbuf >= 3) nbuf -= 3;
            issue_stage(nbuf, ks + 2);
        }

#pragma unroll
        for (int kcl = 0; kcl < 2; kcl++) {
            uint4 a[4], b[2];
#pragma unroll
            for (int i = 0; i < 4; i++)
                a[i] = sA[cur * 512 + ((wm * 4 + i) * 2 + kcl) * 32 + lane];
#pragma unroll
            for (int j = 0; j < 2; j++)
                b[j] = sB[cur * 512 + ((wn * 2 + j) * 2 + kcl) * 32 + lane];
#pragma unroll
            for (int i = 0; i < 4; i++)
#pragma unroll
                for (int j = 0; j < 2; j++) {
                    mma_fp16(acc[i][2 * j],     a[i], b[j].x, b[j].y);
                    mma_fp16(acc[i][2 * j + 1], a[i], b[j].z, b[j].w);
                }
        }
        cur++;
        if (cur == 3) cur = 0;
    }

    const int d = n0 >> 12;
    const float* bih = d ? bihb : bihf;
    const float* bhh = d ? bhhb : bhhf;
    __half* outd = g_xg + (size_t)d * M_ALL * G4;

#pragma unroll
    for (int jj = 0; jj < 4; jj++) {
        int col = n0 + wn * 32 + jj * 8 + 2 * t4;
        int g = col & (G4 - 1);
        float bx = bih[g] + bhh[g];
        float by = bih[g + 1] + bhh[g + 1];
#pragma unroll
        for (int i = 0; i < 4; i++) {
            int row0 = m0 + wm * 64 + i * 16 + gID;
            __half2 v0 = __floats2half2_rn(acc[i][jj][0] + bx, acc[i][jj][1] + by);
            __half2 v1 = __floats2half2_rn(acc[i][jj][2] + bx, acc[i][jj][3] + by);
            *(__half2*)&outd[(size_t)row0 * G4 + g] = v0;
            *(__half2*)&outd[(size_t)(row0 + 8) * G4 + g] = v1;
        }
    }
}

// ---------------------------------------------------------------------------
// Persistent recurrence kernel.
// ---------------------------------------------------------------------------
#define MMA_STEP2(AFRAG, KCI, ACCA, ACCB) do {                      \
    unsigned b00 = *(const unsigned*)(hp0 + (KCI) * 16);            \
    unsigned b01 = *(const unsigned*)(hp0 + (KCI) * 16 + 8);        \
    unsigned b10 = *(const unsigned*)(hp1 + (KCI) * 16);            \
    unsigned b11 = *(const unsigned*)(hp1 + (KCI) * 16 + 8);        \
    mma_fp16((ACCA), (AFRAG), b00, b01);                            \
    mma_fp16((ACCB), (AFRAG), b10, b11);                            \
} while (0)

__global__ __launch_bounds__(THREADS, 1)
void lstm_persistent(const float* __restrict__ Whhf,
                     const float* __restrict__ Whhb,
                     const float* __restrict__ c0f,
                     const float* __restrict__ c0b,
                     float* __restrict__ out) {
    extern __shared__ char smem[];
    uint4*  Wf = (uint4*)smem;
    __half* Hs = (__half*)(smem + SMEM_W);
    float*  Gs = (float*)(smem + SMEM_W + SMEM_HS);

    const int tid = threadIdx.x;
    const int d = blockIdx.x >> 6;
    const int s = blockIdx.x & 63;
    const int j0 = s * 16;
    const float* Whh = d ? Whhb : Whhf;

    for (int s0 = tid; s0 < 4 * 64 * 32; s0 += THREADS) {
        int l  = s0 & 31;
        int kc = (s0 >> 5) & 63;
        int mw = s0 >> 11;
        int r  = l >> 2;
        int t4 = l & 3;
        int row0 = mw * H + j0 + r;
        int row1 = row0 + 8;
        int k0 = kc * 16 + 2 * t4;
        float2 f0 = *(const float2*)&Whh[(size_t)row0 * H + k0];
        float2 f1 = *(const float2*)&Whh[(size_t)row1 * H + k0];
        float2 f2 = *(const float2*)&Whh[(size_t)row0 * H + k0 + 8];
        float2 f3 = *(const float2*)&Whh[(size_t)row1 * H + k0 + 8];
        __half2 h0 = __float22half2_rn(f0);
        __half2 h1 = __float22half2_rn(f1);
        __half2 h2 = __float22half2_rn(f2);
        __half2 h3 = __float22half2_rn(f3);
        uint4 v;
        v.x = *(unsigned*)&h0; v.y = *(unsigned*)&h1;
        v.z = *(unsigned*)&h2; v.w = *(unsigned*)&h3;
        Wf[s0] = v;
    }
    __syncthreads();

    const int warp = tid >> 5;
    const int lane = tid & 31;
    const int mw = warp & 3;
    const int nw = warp >> 2;
    const int gID = lane >> 2;
    const int t4 = lane & 3;
    const uint4* wfrag = Wf + mw * 2048 + lane;
    const __half* hp0 = &Hs[(nw * 16 + gID) * HS_PITCH + 2 * t4];
    const __half* hp1 = hp0 + 8 * HS_PITCH;

    uint4 wreg[NREG];
#pragma unroll
    for (int kc = 0; kc < NREG; kc++) wreg[kc] = wfrag[kc * 32];

    float c_reg[2];
#pragma unroll
    for (int rep = 0; rep < 2; rep++) {
        int id = tid + rep * 256;
        int jj = id & 15;
        int b = id >> 4;
        c_reg[rep] = (d ? c0b : c0f)[b * H + j0 + jj];
    }

    const size_t xg_dir = (size_t)d * M_ALL * G4;

    float xi[2][4];
    {
        int te0 = d ? (T - 1) : 0;
#pragma unroll
        for (int rep = 0; rep < 2; rep++) {
            int id = tid + rep * 256;
            int jj = id & 15;
            int b = id >> 4;
            const __half* xgp = g_xg + xg_dir
                              + (size_t)(te0 * B + b) * G4 + j0 + jj;
            xi[rep][0] = __half2float(__ldcg(xgp));
            xi[rep][1] = __half2float(__ldcg(xgp + H));
            xi[rep][2] = __half2float(__ldcg(xgp + 2 * H));
            xi[rep][3] = __half2float(__ldcg(xgp + 3 * H));
        }
    }

    for (int t = 0; t < T; t++) {
        const int p = t & 1;
        const int t_eff = d ? (T - 1 - t) : t;

        // ---- stage h via cp.async in two k-halves ----
        const uint4* src = (const uint4*)&g_hstage[p][d][0][0];
#pragma unroll
        for (int hh = 0; hh < 2; hh++) {
#pragma unroll
            for (int i = 0; i < 8; i++) {
                int j = tid + i * 256;
                int b = j >> 6;
                int q = (j & 63) + hh * 64;
                unsigned dst = (unsigned)__cvta_generic_to_shared(
                    &Hs[b * HS_PITCH + q * 8]);
                CP_ASYNC16(dst, src + b * 128 + q);
            }
            CP_COMMIT();
        }

        float acc0[4] = {0.f, 0.f, 0.f, 0.f};   // n-lo, even kc
        float acc1[4] = {0.f, 0.f, 0.f, 0.f};   // n-hi, even kc
        float acc2[4] = {0.f, 0.f, 0.f, 0.f};   // n-lo, odd kc
        float acc3[4] = {0.f, 0.f, 0.f, 0.f};   // n-hi, odd kc

        CP_WAIT1();
        __syncthreads();
#pragma unroll
        for (int kc = 0; kc < 32; kc += 2) {
            MMA_STEP2(wreg[kc],     kc,     acc0, acc1);
            MMA_STEP2(wreg[kc + 1], kc + 1, acc2, acc3);
        }

        CP_WAIT0();
        __syncthreads();
#pragma unroll
        for (int kc = 32; kc < NREG; kc += 2) {
            MMA_STEP2(wreg[kc],     kc,     acc0, acc1);
            MMA_STEP2(wreg[kc + 1], kc + 1, acc2, acc3);
        }
#pragma unroll 8
        for (int kc = NREG; kc < 64; kc += 2) {
            uint4 a0 = wfrag[kc * 32];
            uint4 a1 = wfrag[(kc + 1) * 32];
            MMA_STEP2(a0, kc,     acc0, acc1);
            MMA_STEP2(a1, kc + 1, acc2, acc3);
        }

#pragma unroll
        for (int q = 0; q < 4; q++) {
            acc0[q] += acc2[q];
            acc1[q] += acc3[q];
        }

        {
            int row = mw * 16 + gID;
            int cb = nw * 16 + 2 * t4;
            Gs[row * 33 + cb]           = acc0[0];
            Gs[row * 33 + cb + 1]       = acc0[1];
            Gs[(row + 8) * 33 + cb]     = acc0[2];
            Gs[(row + 8) * 33 + cb + 1] = acc0[3];
            Gs[row * 33 + cb + 8]       = acc1[0];
            Gs[row * 33 + cb + 9]       = acc1[1];
            Gs[(row + 8) * 33 + cb + 8] = acc1[2];
            Gs[(row + 8) * 33 + cb + 9] = acc1[3];
        }
        __syncthreads();

        float hn_keep[2];
#pragma unroll
        for (int rep = 0; rep < 2; rep++) {
            int id = tid + rep * 256;
            int jj = id & 15;
            int b = id >> 4;
            float ig = Gs[(0  + jj) * 33 + b] + xi[rep][0];
            float fg = Gs[(16 + jj) * 33 + b] + xi[rep][1];
            float gg = Gs[(32 + jj) * 33 + b] + xi[rep][2];
            float og = Gs[(48 + jj) * 33 + b] + xi[rep][3];
            ig = sig_(ig);
            fg = sig_(fg);
            og = sig_(og);
            gg = tanh_(gg);
            float cn = fg * c_reg[rep] + ig * gg;
            c_reg[rep] = cn;
            float hn = og * tanh_(cn);
            hn_keep[rep] = hn;
            g_hstage[p ^ 1][d][b][j0 + jj] = __float2half(hn);
        }

        __syncthreads();    // hstage stores ordered CTA-wide before release

        if (t + 1 < T && tid == 0) red_release_add(&g_bar[d]);

        // hidden behind the barrier: out store + next xg prefetch
#pragma unroll
        for (int rep = 0; rep < 2; rep++) {
            int id = tid + rep * 256;
            int jj = id & 15;
            int b = id >> 4;
            out[(size_t)t_eff * B * OUT_COLS + (size_t)b * OUT_COLS
                + (size_t)d * H + j0 + jj] = hn_keep[rep];
        }
        if (t + 1 < T) {
            int ten = d ? (T - 2 - t) : (t + 1);
#pragma unroll
            for (int rep = 0; rep < 2; rep++) {
                int id = tid + rep * 256;
                int jj = id & 15;
                int b = id >> 4;
                const __half* xgp = g_xg + xg_dir
                                  + (size_t)(ten * B + b) * G4 + j0 + jj;
                xi[rep][0] = __half2float(__ldcg(xgp));
                xi[rep][1] = __half2float(__ldcg(xgp + H));
                xi[rep][2] = __half2float(__ldcg(xgp + 2 * H));
                xi[rep][3] = __half2float(__ldcg(xgp + 3 * H));
            }
            if (tid == 0) {
                unsigned tgt = (unsigned)CTAS_PER_DIR * (t + 1);
                while (ld_acquire(&g_bar[d]) < tgt) { }
            }
            __syncthreads();
        }
    }

#pragma unroll
    for (int rep = 0; rep < 2; rep++) {
        int id = tid + rep * 256;
        int jj = id & 15;
        int b = id >> 4;
        g_c[(size_t)d * B * H + (size_t)b * H + j0 + jj] = c_reg[rep];
    }
}

// ---------------------------------------------------------------------------
__global__ void finalize_kernel(float* __restrict__ out) {
    int i = blockIdx.x * blockDim.x + threadIdx.x;
    if (i >= B * H) return;
    int b = i >> 10;
    int j = i & (H - 1);
    float* tail = out + OUT_MAIN;
    tail[i]             = out[(size_t)(T - 1) * B * OUT_COLS + (size_t)b * OUT_COLS + j];
    tail[B * H + i]     = g_c[i];
    tail[2 * B * H + i] = out[(size_t)b * OUT_COLS + H + j];
    tail[3 * B * H + i] = g_c[B * H + i];
}

// ---------------------------------------------------------------------------
extern "C" void kernel_launch(void* const* d_in, const int* in_sizes, int n_in,
                              void* d_out, int out_size) {
    const float* x    = (const float*)d_in[0];
    const float* h0f  = (const float*)d_in[1];
    const float* c0f  = (const float*)d_in[2];
    const float* h0b  = (const float*)d_in[3];
    const float* c0b  = (const float*)d_in[4];
    const float* Wihf = (const float*)d_in[5];
    const float* Whhf = (const float*)d_in[6];
    const float* bihf = (const float*)d_in[7];
    const float* bhhf = (const float*)d_in[8];
    const float* Wihb = (const float*)d_in[9];
    const float* Whhb = (const float*)d_in[10];
    const float* bihb = (const float*)d_in[11];
    const float* bhhb = (const float*)d_in[12];
    float* out = (float*)d_out;

    static int smem_set = 0;
    if (!smem_set) {
        cudaFuncSetAttribute(lstm_persistent,
                             cudaFuncAttributeMaxDynamicSharedMemorySize,
                             SMEM_BYTES);
        cudaFuncSetAttribute(xg_gemm_hmma,
                             cudaFuncAttributeMaxDynamicSharedMemorySize,
                             GEMM_SMEM);
        smem_set = 1;
    }

    init_kernel<<<(B * H + 255) / 256, 256>>>(h0f, h0b);
    prepack_x<<<(M16 * KC * 32 + 255) / 256, 256>>>(x);
    prepack_w<<<(N16 * KC * 32 + 255) / 256, 256>>>(Wihf, Wihb);

    dim3 grid_xg(N_ALL / 128, M_ALL / 128);   // (64, 128)
    xg_gemm_hmma<<<grid_xg, 256, GEMM_SMEM>>>(bihf, bhhf, bihb, bhhb);

    lstm_persistent<<<CTAS, THREADS, SMEM_BYTES>>>(Whhf, Whhb, c0f, c0b, out);

    finalize_kernel<<<(B * H + 255) / 256, 256>>>(out);
}

// round 8
// speedup vs baseline: 8.5352x; 1.0042x over previous
#include <cuda_runtime.h>
#include <cuda_fp16.h>
#include <math.h>

// ---------------------------------------------------------------------------
// Bidirectional LSTM: T=512, B=32, I=1024, H=1024.
// Round 8 (tcgen05 unavailable on this build target -> legacy mma.sync):
//   - recurrence: warps split by k-half; each warp m16 x n32(full batch),
//     ALL 32 W k-chunks register-resident (zero W smem traffic);
//     k-halves reduced via two Gs buffers in the pointwise.
//   - xg GEMM: BK=64 (16 k-steps, half the syncs), 3-stage cp.async.
// ---------------------------------------------------------------------------

namespace {
constexpr int T = 512;
constexpr int B = 32;
constexpr int I = 1024;
constexpr int H = 1024;
constexpr int G4 = 4 * H;          // 4096
constexpr int N_ALL = 2 * G4;      // 8192
constexpr int OUT_COLS = 2 * H;    // 2048
constexpr int M_ALL = T * B;       // 16384
constexpr long long OUT_MAIN = (long long)T * B * OUT_COLS;

constexpr int CTAS = 128;          // 2 dirs x 64 slices of 16 units
constexpr int THREADS = 256;
constexpr int CTAS_PER_DIR = 64;

constexpr int HS_PITCH = 1032;     // halves; conflict-free fragment loads
constexpr int SMEM_W  = 4 * 64 * 32 * 16;           // 131072 (prologue only)
constexpr int SMEM_HS = 32 * HS_PITCH * 2;          // 66048
constexpr int SMEM_G0 = SMEM_W + SMEM_HS;
constexpr int SMEM_G1 = SMEM_G0 + 64 * 33 * 4;      // second k-half buffer
constexpr int SMEM_BYTES = SMEM_G1 + 64 * 33 * 4;   // 214016

constexpr int KC = 64;
constexpr int M16 = M_ALL / 16;    // 1024
constexpr int N16 = N_ALL / 16;    // 512

constexpr int GEMM_SMEM = 3 * 2048 * 16;            // 98304 (BK=64, 3-stage)
}

__device__ __half g_xg[2LL * M_ALL * G4];
__device__ float g_c[2 * B * H];
__device__ __half g_hstage[2][2][B][H];
__device__ unsigned g_bar[2];
__device__ uint4 g_xa[(long long)M16 * KC * 32];
__device__ uint4 g_wb[(long long)N16 * KC * 32];

__device__ __forceinline__ void mma_fp16(float* d, const uint4& a,
                                         unsigned b0, unsigned b1) {
    asm volatile(
        "mma.sync.aligned.m16n8k16.row.col.f32.f16.f16.f32 "
        "{%0,%1,%2,%3}, {%4,%5,%6,%7}, {%8,%9}, {%0,%1,%2,%3};"
        : "+f"(d[0]), "+f"(d[1]), "+f"(d[2]), "+f"(d[3])
        : "r"(a.x), "r"(a.y), "r"(a.z), "r"(a.w), "r"(b0), "r"(b1));
}

__device__ __forceinline__ float sig_(float x) {
    return 1.f / (1.f + __expf(-x));
}
__device__ __forceinline__ float tanh_(float x) {
    float t = __expf(-2.f * fabsf(x));
    float r = (1.f - t) / (1.f + t);
    return x < 0.f ? -r : r;
}

__device__ __forceinline__ void red_release_add(unsigned* p) {
    asm volatile("red.release.gpu.global.add.u32 [%0], %1;"
                 :: "l"(p), "r"(1u) : "memory");
}
__device__ __forceinline__ unsigned ld_acquire(const unsigned* p) {
    unsigned v;
    asm volatile("ld.acquire.gpu.global.u32 %0, [%1];"
                 : "=r"(v) : "l"(p) : "memory");
    return v;
}

#define CP_ASYNC16(smem_u32, gptr) \
    asm volatile("cp.async.cg.shared.global [%0], [%1], 16;" \
                 :: "r"(smem_u32), "l"(gptr))
#define CP_COMMIT() asm volatile("cp.async.commit_group;")
#define CP_WAIT1() asm volatile("cp.async.wait_group 1;")
#define CP_WAIT0() asm volatile("cp.async.wait_group 0;")

// ---------------------------------------------------------------------------
__global__ void init_kernel(const float* __restrict__ h0f,
                            const float* __restrict__ h0b) {
    int i = blockIdx.x * blockDim.x + threadIdx.x;
    if (i == 0) { g_bar[0] = 0; g_bar[1] = 0; }
    if (i < B * H) {
        int b = i >> 10;
        int k = i & 1023;
        g_hstage[0][0][b][k] = __float2half(h0f[i]);
        g_hstage[0][1][b][k] = __float2half(h0b[i]);
    }
}

// ---------------------------------------------------------------------------
__global__ void prepack_x(const float* __restrict__ x) {
    int idx = blockIdx.x * blockDim.x + threadIdx.x;
    if (idx >= M16 * KC * 32) return;
    int lane = idx & 31;
    int kc = (idx >> 5) & 63;
    int m16 = idx >> 11;
    int r = lane >> 2;
    int t4 = lane & 3;
    int m0 = m16 * 16;
    int k0 = kc * 16 + 2 * t4;
    float2 f0 = *(const float2*)&x[(size_t)(m0 + r) * I + k0];
    float2 f1 = *(const float2*)&x[(size_t)(m0 + r + 8) * I + k0];
    float2 f2 = *(const float2*)&x[(size_t)(m0 + r) * I + k0 + 8];
    float2 f3 = *(const float2*)&x[(size_t)(m0 + r + 8) * I + k0 + 8];
    __half2 h0 = __float22half2_rn(f0);
    __half2 h1 = __float22half2_rn(f1);
    __half2 h2 = __float22half2_rn(f2);
    __half2 h3 = __float22half2_rn(f3);
    uint4 v;
    v.x = *(unsigned*)&h0; v.y = *(unsigned*)&h1;
    v.z = *(unsigned*)&h2; v.w = *(unsigned*)&h3;
    g_xa[idx] = v;
}

__global__ void prepack_w(const float* __restrict__ Wf,
                          const float* __restrict__ Wb) {
    int idx = blockIdx.x * blockDim.x + threadIdx.x;
    if (idx >= N16 * KC * 32) return;
    int lane = idx & 31;
    int kc = (idx >> 5) & 63;
    int n16 = idx >> 11;
    int n = n16 * 16;
    const float* W = (n >= G4) ? Wb : Wf;
    int g = n & (G4 - 1);
    int r = lane >> 2;
    int t4 = lane & 3;
    int k0 = kc * 16 + 2 * t4;
    float2 f0 = *(const float2*)&W[(size_t)(g + r) * H + k0];
    float2 f1 = *(const float2*)&W[(size_t)(g + r) * H + k0 + 8];
    float2 f2 = *(const float2*)&W[(size_t)(g + r + 8) * H + k0];
    float2 f3 = *(const float2*)&W[(size_t)(g + r + 8) * H + k0 + 8];
    __half2 h0 = __float22half2_rn(f0);
    __half2 h1 = __float22half2_rn(f1);
    __half2 h2 = __float22half2_rn(f2);
    __half2 h3 = __float22half2_rn(f3);
    uint4 v;
    v.x = *(unsigned*)&h0; v.y = *(unsigned*)&h1;
    v.z = *(unsigned*)&h2; v.w = *(unsigned*)&h3;
    g_wb[idx] = v;
}

// ---------------------------------------------------------------------------
// xg GEMM: CTA tile 128x128, 8 warps m64n32, BK=64 (4 k16 per step),
// 3-stage cp.async, 2 CTAs/SM. grid = (64, 128).
// ---------------------------------------------------------------------------
__global__ __launch_bounds__(256, 2)
void xg_gemm_hmma(const float* __restrict__ bihf, const float* __restrict__ bhhf,
                  const float* __restrict__ bihb, const float* __restrict__ bhhb) {
    extern __shared__ char gsm[];
    uint4* sA = (uint4*)gsm;                    // 3 x 1024
    uint4* sB = (uint4*)(gsm + 3 * 16384);      // 3 x 1024

    const int tid = threadIdx.x;
    const int m0 = blockIdx.y * 128;
    const int n0 = blockIdx.x * 128;
    const int m16g0 = m0 >> 4;
    const int n16g0 = n0 >> 4;

    const int warp = tid >> 5;
    const int lane = tid & 31;
    const int wm = warp >> 2;       // 0..1
    const int wn = warp & 3;        // 0..3
    const int gID = lane >> 2;
    const int t4 = lane & 3;

    float acc[4][4][4];
#pragma unroll
    for (int i = 0; i < 4; i++)
#pragma unroll
        for (int j = 0; j < 4; j++)
#pragma unroll
            for (int q = 0; q < 4; q++) acc[i][j][q] = 0.f;

    // copy indices: 4 uint4 each for A and B per thread per stage
    int c_16l[4], c_kcl[4], c_lane[4];
#pragma unroll
    for (int j = 0; j < 4; j++) {
        int i = tid + j * 256;
        c_16l[j] = i >> 7;
        c_kcl[j] = (i >> 5) & 3;
        c_lane[j] = i & 31;
    }

    auto issue_stage = [&](int buf, int ks) {
#pragma unroll
        for (int j = 0; j < 4; j++) {
            const uint4* src = g_xa +
                ((size_t)(m16g0 + c_16l[j]) * KC + ks * 4 + c_kcl[j]) * 32 + c_lane[j];
            unsigned dst = (unsigned)__cvta_generic_to_shared(
                &sA[buf * 1024 + (c_16l[j] * 4 + c_kcl[j]) * 32 + c_lane[j]]);
            CP_ASYNC16(dst, src);
        }
#pragma unroll
        for (int j = 0; j < 4; j++) {
            const uint4* src = g_wb +
                ((size_t)(n16g0 + c_16l[j]) * KC + ks * 4 + c_kcl[j]) * 32 + c_lane[j];
            unsigned dst = (unsigned)__cvta_generic_to_shared(
                &sB[buf * 1024 + (c_16l[j] * 4 + c_kcl[j]) * 32 + c_lane[j]]);
            CP_ASYNC16(dst, src);
        }
        CP_COMMIT();
    };

    issue_stage(0, 0);
    issue_stage(1, 1);

    int cur = 0;
    for (int ks = 0; ks < 16; ks++) {
        if (ks < 15) { CP_WAIT1(); } else { CP_WAIT0(); }
        __syncthreads();
        if (ks + 2 < 16) {
            int nbuf = cur + 2;
            if (nbuf >= 3) nbuf -= 3;
            issue_stage(nbuf, ks + 2);
        }

#pragma unroll
        for (int kcl = 0; kcl < 4; kcl++) {
            uint4 a[4], b[2];
#pragma unroll
            for (int i = 0; i < 4; i++)
                a[i] = sA[cur * 1024 + ((wm * 4 + i) * 4 + kcl) * 32 + lane];
#pragma unroll
            for (int j = 0; j < 2; j++)
                b[j] = sB[cur * 1024 + ((wn * 2 + j) * 4 + kcl) * 32 + lane];
#pragma unroll
            for (int i = 0; i < 4; i++)
#pragma unroll
                for (int j = 0; j < 2; j++) {
                    mma_fp16(acc[i][2 * j],     a[i], b[j].x, b[j].y);
                    mma_fp16(acc[i][2 * j + 1], a[i], b[j].z, b[j].w);
                }
        }
        cur++;
        if (cur == 3) cur = 0;
    }

    const int d = n0 >> 12;
    const float* bih = d ? bihb : bihf;
    const float* bhh = d ? bhhb : bhhf;
    __half* outd = g_xg + (size_t)d * M_ALL * G4;

#pragma unroll
    for (int jj = 0; jj < 4; jj++) {
        int col = n0 + wn * 32 + jj * 8 + 2 * t4;
        int g = col & (G4 - 1);
        float bx = bih[g] + bhh[g];
        float by = bih[g + 1] + bhh[g + 1];
#pragma unroll
        for (int i = 0; i < 4; i++) {
            int row0 = m0 + wm * 64 + i * 16 + gID;
            __half2 v0 = __floats2half2_rn(acc[i][jj][0] + bx, acc[i][jj][1] + by);
            __half2 v1 = __floats2half2_rn(acc[i][jj][2] + bx, acc[i][jj][3] + by);
            *(__half2*)&outd[(size_t)row0 * G4 + g] = v0;
            *(__half2*)&outd[(size_t)(row0 + 8) * G4 + g] = v1;
        }
    }
}

// ---------------------------------------------------------------------------
// Persistent recurrence kernel. grid=128, block=256, 1 CTA/SM.
// Warp = (mw = gate 0..3, kh = k-half 0..1); each warp m16 x n32, 32 kc,
// all W fragments in registers. k-halves reduced via Gs0/Gs1 in pointwise.
// ---------------------------------------------------------------------------
__global__ __launch_bounds__(THREADS, 1)
void lstm_persistent(const float* __restrict__ Whhf,
                     const float* __restrict__ Whhb,
                     const float* __restrict__ c0f,
                     const float* __restrict__ c0b,
                     float* __restrict__ out) {
    extern __shared__ char smem[];
    uint4*  Wf = (uint4*)smem;                       // prologue staging only
    __half* Hs = (__half*)(smem + SMEM_W);
    float*  Gs0 = (float*)(smem + SMEM_G0);
    float*  Gs1 = (float*)(smem + SMEM_G1);

    const int tid = threadIdx.x;
    const int d = blockIdx.x >> 6;
    const int s = blockIdx.x & 63;
    const int j0 = s * 16;
    const float* Whh = d ? Whhb : Whhf;

    // ---- prepack W slice into fp16 fragment layout (smem, prologue) ----
    for (int s0 = tid; s0 < 4 * 64 * 32; s0 += THREADS) {
        int l  = s0 & 31;
        int kc = (s0 >> 5) & 63;
        int mw = s0 >> 11;
        int r  = l >> 2;
        int t4 = l & 3;
        int row0 = mw * H + j0 + r;
        int row1 = row0 + 8;
        int k0 = kc * 16 + 2 * t4;
        float2 f0 = *(const float2*)&Whh[(size_t)row0 * H + k0];
        float2 f1 = *(const float2*)&Whh[(size_t)row1 * H + k0];
        float2 f2 = *(const float2*)&Whh[(size_t)row0 * H + k0 + 8];
        float2 f3 = *(const float2*)&Whh[(size_t)row1 * H + k0 + 8];
        __half2 h0 = __float22half2_rn(f0);
        __half2 h1 = __float22half2_rn(f1);
        __half2 h2 = __float22half2_rn(f2);
        __half2 h3 = __float22half2_rn(f3);
        uint4 v;
        v.x = *(unsigned*)&h0; v.y = *(unsigned*)&h1;
        v.z = *(unsigned*)&h2; v.w = *(unsigned*)&h3;
        Wf[s0] = v;
    }
    __syncthreads();

    const int warp = tid >> 5;
    const int lane = tid & 31;
    const int mw = warp & 3;            // gate / m16 tile
    const int kh = warp >> 2;           // k-half 0/1
    const int gID = lane >> 2;
    const int t4 = lane & 3;

    // ---- load this warp's 32 W k-chunks fully into registers ----
    const uint4* wfrag = Wf + mw * 2048 + kh * 32 * 32 + lane;
    uint4 wreg[32];
#pragma unroll
    for (int i = 0; i < 32; i++) wreg[i] = wfrag[i * 32];

    // B fragment base pointers (4 n8 tiles covering batch 0..31), k-half folded
    const __half* hp0 = &Hs[(0 * 8 + gID) * HS_PITCH + 2 * t4] + kh * 32 * 16;
    const __half* hp1 = &Hs[(1 * 8 + gID) * HS_PITCH + 2 * t4] + kh * 32 * 16;
    const __half* hp2 = &Hs[(2 * 8 + gID) * HS_PITCH + 2 * t4] + kh * 32 * 16;
    const __half* hp3 = &Hs[(3 * 8 + gID) * HS_PITCH + 2 * t4] + kh * 32 * 16;
    float* Gw = kh ? Gs1 : Gs0;

    float c_reg[2];
#pragma unroll
    for (int rep = 0; rep < 2; rep++) {
        int id = tid + rep * 256;
        int jj = id & 15;
        int b = id >> 4;
        c_reg[rep] = (d ? c0b : c0f)[b * H + j0 + jj];
    }

    const size_t xg_dir = (size_t)d * M_ALL * G4;

    float xi[2][4];
    {
        int te0 = d ? (T - 1) : 0;
#pragma unroll
        for (int rep = 0; rep < 2; rep++) {
            int id = tid + rep * 256;
            int jj = id & 15;
            int b = id >> 4;
            const __half* xgp = g_xg + xg_dir
                              + (size_t)(te0 * B + b) * G4 + j0 + jj;
            xi[rep][0] = __half2float(__ldcg(xgp));
            xi[rep][1] = __half2float(__ldcg(xgp + H));
            xi[rep][2] = __half2float(__ldcg(xgp + 2 * H));
            xi[rep][3] = __half2float(__ldcg(xgp + 3 * H));
        }
    }

    for (int t = 0; t < T; t++) {
        const int p = t & 1;
        const int t_eff = d ? (T - 1 - t) : t;

        // ---- stage h (fp16) into Hs via cp.async ----
        const uint4* src = (const uint4*)&g_hstage[p][d][0][0];
#pragma unroll
        for (int i = 0; i < 16; i++) {
            int j = tid + i * 256;           // 0..4095
            int b = j >> 7;
            int q = j & 127;
            unsigned dst = (unsigned)__cvta_generic_to_shared(
                &Hs[b * HS_PITCH + q * 8]);
            CP_ASYNC16(dst, src + b * 128 + q);
        }
        CP_COMMIT();
        CP_WAIT0();
        __syncthreads();

        // ---- 32 kc, 4 n8 accumulator chains, W from registers ----
        float a0[4] = {0.f, 0.f, 0.f, 0.f};
        float a1[4] = {0.f, 0.f, 0.f, 0.f};
        float a2[4] = {0.f, 0.f, 0.f, 0.f};
        float a3[4] = {0.f, 0.f, 0.f, 0.f};
#pragma unroll
        for (int i = 0; i < 32; i++) {
            unsigned b00 = *(const unsigned*)(hp0 + i * 16);
            unsigned b01 = *(const unsigned*)(hp0 + i * 16 + 8);
            mma_fp16(a0, wreg[i], b00, b01);
            unsigned b10 = *(const unsigned*)(hp1 + i * 16);
            unsigned b11 = *(const unsigned*)(hp1 + i * 16 + 8);
            mma_fp16(a1, wreg[i], b10, b11);
            unsigned b20 = *(const unsigned*)(hp2 + i * 16);
            unsigned b21 = *(const unsigned*)(hp2 + i * 16 + 8);
            mma_fp16(a2, wreg[i], b20, b21);
            unsigned b30 = *(const unsigned*)(hp3 + i * 16);
            unsigned b31 = *(const unsigned*)(hp3 + i * 16 + 8);
            mma_fp16(a3, wreg[i], b30, b31);
        }

        // ---- stage gate pre-activations (per k-half buffer) ----
        {
            int row = mw * 16 + gID;
            int cb = 2 * t4;
            float* r0 = Gw + row * 33;
            float* r1 = Gw + (row + 8) * 33;
            r0[cb]          = a0[0]; r0[cb + 1]      = a0[1];
            r1[cb]          = a0[2]; r1[cb + 1]      = a0[3];
            r0[cb + 8]      = a1[0]; r0[cb + 9]      = a1[1];
            r1[cb + 8]      = a1[2]; r1[cb + 9]      = a1[3];
            r0[cb + 16]     = a2[0]; r0[cb + 17]     = a2[1];
            r1[cb + 16]     = a2[2]; r1[cb + 17]     = a2[3];
            r0[cb + 24]     = a3[0]; r0[cb + 25]     = a3[1];
            r1[cb + 24]     = a3[2]; r1[cb + 25]     = a3[3];
        }
        __syncthreads();

        // ---- pointwise cell update ----
        float hn_keep[2];
#pragma unroll
        for (int rep = 0; rep < 2; rep++) {
            int id = tid + rep * 256;
            int jj = id & 15;
            int b = id >> 4;
            float ig = Gs0[(0  + jj) * 33 + b] + Gs1[(0  + jj) * 33 + b] + xi[rep][0];
            float fg = Gs0[(16 + jj) * 33 + b] + Gs1[(16 + jj) * 33 + b] + xi[rep][1];
            float gg = Gs0[(32 + jj) * 33 + b] + Gs1[(32 + jj) * 33 + b] + xi[rep][2];
            float og = Gs0[(48 + jj) * 33 + b] + Gs1[(48 + jj) * 33 + b] + xi[rep][3];
            ig = sig_(ig);
            fg = sig_(fg);
            og = sig_(og);
            gg = tanh_(gg);
            float cn = fg * c_reg[rep] + ig * gg;
            c_reg[rep] = cn;
            float hn = og * tanh_(cn);
            hn_keep[rep] = hn;
            g_hstage[p ^ 1][d][b][j0 + jj] = __float2half(hn);
        }

        __syncthreads();    // hstage stores ordered CTA-wide before release

        if (t + 1 < T && tid == 0) red_release_add(&g_bar[d]);

        // hidden behind the barrier: out store + next xg prefetch
#pragma unroll
        for (int rep = 0; rep < 2; rep++) {
            int id = tid + rep * 256;
            int jj = id & 15;
            int b = id >> 4;
            out[(size_t)t_eff * B * OUT_COLS + (size_t)b * OUT_COLS
                + (size_t)d * H + j0 + jj] = hn_keep[rep];
        }
        if (t + 1 < T) {
            int ten = d ? (T - 2 - t) : (t + 1);
#pragma unroll
            for (int rep = 0; rep < 2; rep++) {
                int id = tid + rep * 256;
                int jj = id & 15;
                int b = id >> 4;
                const __half* xgp = g_xg + xg_dir
                                  + (size_t)(ten * B + b) * G4 + j0 + jj;
                xi[rep][0] = __half2float(__ldcg(xgp));
                xi[rep][1] = __half2float(__ldcg(xgp + H));
                xi[rep][2] = __half2float(__ldcg(xgp + 2 * H));
                xi[rep][3] = __half2float(__ldcg(xgp + 3 * H));
            }
            if (tid == 0) {
                unsigned tgt = (unsigned)CTAS_PER_DIR * (t + 1);
                while (ld_acquire(&g_bar[d]) < tgt) { }
            }
            __syncthreads();
        }
    }

#pragma unroll
    for (int rep = 0; rep < 2; rep++) {
        int id = tid + rep * 256;
        int jj = id & 15;
        int b = id >> 4;
        g_c[(size_t)d * B * H + (size_t)b * H + j0 + jj] = c_reg[rep];
    }
}

// ---------------------------------------------------------------------------
__global__ void finalize_kernel(float* __restrict__ out) {
    int i = blockIdx.x * blockDim.x + threadIdx.x;
    if (i >= B * H) return;
    int b = i >> 10;
    int j = i & (H - 1);
    float* tail = out + OUT_MAIN;
    tail[i]             = out[(size_t)(T - 1) * B * OUT_COLS + (size_t)b * OUT_COLS + j];
    tail[B * H + i]     = g_c[i];
    tail[2 * B * H + i] = out[(size_t)b * OUT_COLS + H + j];
    tail[3 * B * H + i] = g_c[B * H + i];
}

// ---------------------------------------------------------------------------
extern "C" void kernel_launch(void* const* d_in, const int* in_sizes, int n_in,
                              void* d_out, int out_size) {
    const float* x    = (const float*)d_in[0];
    const float* h0f  = (const float*)d_in[1];
    const float* c0f  = (const float*)d_in[2];
    const float* h0b  = (const float*)d_in[3];
    const float* c0b  = (const float*)d_in[4];
    const float* Wihf = (const float*)d_in[5];
    const float* Whhf = (const float*)d_in[6];
    const float* bihf = (const float*)d_in[7];
    const float* bhhf = (const float*)d_in[8];
    const float* Wihb = (const float*)d_in[9];
    const float* Whhb = (const float*)d_in[10];
    const float* bihb = (const float*)d_in[11];
    const float* bhhb = (const float*)d_in[12];
    float* out = (float*)d_out;

    static int smem_set = 0;
    if (!smem_set) {
        cudaFuncSetAttribute(lstm_persistent,
                             cudaFuncAttributeMaxDynamicSharedMemorySize,
                             SMEM_BYTES);
        cudaFuncSetAttribute(xg_gemm_hmma,
                             cudaFuncAttributeMaxDynamicSharedMemorySize,
                             GEMM_SMEM);
        smem_set = 1;
    }

    init_kernel<<<(B * H + 255) / 256, 256>>>(h0f, h0b);
    prepack_x<<<(M16 * KC * 32 + 255) / 256, 256>>>(x);
    prepack_w<<<(N16 * KC * 32 + 255) / 256, 256>>>(Wihf, Wihb);

    dim3 grid_xg(N_ALL / 128, M_ALL / 128);   // (64, 128)
    xg_gemm_hmma<<<grid_xg, 256, GEMM_SMEM>>>(bihf, bhhf, bihb, bhhb);

    lstm_persistent<<<CTAS, THREADS, SMEM_BYTES>>>(Whhf, Whhb, c0f, c0b, out);

    finalize_kernel<<<(B * H + 255) / 256, 256>>>(out);
}